// round 4
// baseline (speedup 1.0000x reference)
#include <cuda_runtime.h>
#include <cuda_bf16.h>

// ---------------------------------------------------------------------------
// VQ-VAE forward on GB300 (sm_103a).
// Round 3: bit-replicate the reference quantizer arithmetic:
//   d = fl( fl(znorm - fl(2*dot)) + cnorm ), dot = sequential fp32 FMA k=0..127,
//   znorm/cnorm = XLA warp row-reduction association, lexicographic argmin,
//   straight-through output fl(z + fl(q - z)).
// Convs: direct f32x2-packed FMA, smem-tiled (unchanged from R2).
// ---------------------------------------------------------------------------

#define ULL unsigned long long

__device__ __forceinline__ ULL pack2(float a, float b) {
    ULL r; asm("mov.b64 %0, {%1, %2};" : "=l"(r) : "f"(a), "f"(b)); return r;
}
__device__ __forceinline__ void unpack2(ULL v, float& a, float& b) {
    asm("mov.b64 {%0, %1}, %2;" : "=f"(a), "=f"(b) : "l"(v));
}
__device__ __forceinline__ ULL fma2(ULL a, ULL b, ULL c) {
    ULL d; asm("fma.rn.f32x2 %0, %1, %2, %3;" : "=l"(d) : "l"(a), "l"(b), "l"(c)); return d;
}

// Scratch buffers (max tensor: 8 x 128 x 256 x 256 fp32 = 256 MB each)
__device__ float g_bufA[8 * 128 * 256 * 256];
__device__ float g_bufB[8 * 128 * 256 * 256];
__device__ float g_bufC[8 * 128 * 256 * 256];
__device__ float g_cbT[128 * 1024];   // codebook transposed: [k][code]
__device__ float g_cnorm[1024];
__device__ double g_loss;

// ---------------------------------------------------------------------------
// Direct 3x3 conv, NCHW. Block: 16x16 threads over a 16x16 output tile.
// Each thread computes OUTC output channels (as OUTC/2 f32x2 accumulators).
// SKIP: 0 = none, 1 = identity skip add, 2 = 1x1-conv skip add.
// UPS: input is nearest-2x upsampled on the fly.
// ---------------------------------------------------------------------------
template <int CIN, int OUTC, int STRIDE, bool RELU, int SKIP, bool UPS>
__global__ void __launch_bounds__(256) conv3x3_k(
    const float* __restrict__ in, const float* __restrict__ wgt,
    const float* __restrict__ bias,
    const float* __restrict__ skip_in, const float* __restrict__ skip_w,
    const float* __restrict__ skip_b,
    float* __restrict__ out,
    int IH, int IW, int OH, int OW, int COUT, int CSKIP, int nG)
{
    constexpr int TS = 16 * STRIDE + 2;
    constexpr int NP = OUTC / 2;
    __shared__ float tile[TS * TS];
    __shared__ ULL ws2[9 * NP];

    const int tx = threadIdx.x, ty = threadIdx.y;
    const int tid = ty * 16 + tx;
    const int bz = blockIdx.z;
    const int b = bz / nG;
    const int co0 = (bz - b * nG) * OUTC;
    const int oy = blockIdx.y * 16 + ty;
    const int ox = blockIdx.x * 16 + tx;
    const int y0 = blockIdx.y * 16 * STRIDE - 1;
    const int x0 = blockIdx.x * 16 * STRIDE - 1;
    const int DH = UPS ? IH * 2 : IH;
    const int DW = UPS ? IW * 2 : IW;

    ULL acc[NP];
#pragma unroll
    for (int p = 0; p < NP; p++) acc[p] = 0ull;

#pragma unroll 1
    for (int ci = 0; ci < CIN; ci++) {
        const float* inc = in + (b * CIN + ci) * IH * IW;
        for (int i = tid; i < TS * TS; i += 256) {
            int sy = i / TS, sx = i - sy * TS;
            int gy = y0 + sy, gx = x0 + sx;
            float v = 0.f;
            if ((unsigned)gy < (unsigned)DH && (unsigned)gx < (unsigned)DW) {
                int iy = UPS ? (gy >> 1) : gy;
                int ix = UPS ? (gx >> 1) : gx;
                v = inc[iy * IW + ix];
            }
            tile[i] = v;
        }
        if (tid < 9 * NP) {
            int k = tid / NP, p = tid - k * NP;
            int ca = co0 + 2 * p;
            float wa = (ca < COUT) ? wgt[(ca * CIN + ci) * 9 + k] : 0.f;
            float wb = (ca + 1 < COUT) ? wgt[((ca + 1) * CIN + ci) * 9 + k] : 0.f;
            ws2[tid] = pack2(wa, wb);
        }
        __syncthreads();

#pragma unroll
        for (int ky = 0; ky < 3; ky++) {
#pragma unroll
            for (int kx = 0; kx < 3; kx++) {
                float v = tile[(ty * STRIDE + ky) * TS + tx * STRIDE + kx];
                ULL vv = pack2(v, v);
                const ULL* wrow = &ws2[(ky * 3 + kx) * NP];
#pragma unroll
                for (int p = 0; p < NP; p++) acc[p] = fma2(vv, wrow[p], acc[p]);
            }
        }
        __syncthreads();
    }

    float accf[OUTC];
#pragma unroll
    for (int p = 0; p < NP; p++) unpack2(acc[p], accf[2 * p], accf[2 * p + 1]);

    if (SKIP == 2) {
#pragma unroll 1
        for (int cs = 0; cs < CSKIP; cs++) {
            float sv = skip_in[((b * CSKIP + cs) * OH + oy) * OW + ox];
#pragma unroll
            for (int c = 0; c < OUTC; c++) {
                accf[c] += sv * skip_w[(co0 + c) * CSKIP + cs];
            }
        }
    }

#pragma unroll
    for (int c = 0; c < OUTC; c++) {
        int co = co0 + c;
        if (co >= COUT) break;
        float a = accf[c] + bias[co];
        if (SKIP == 1) a += skip_in[((b * COUT + co) * OH + oy) * OW + ox];
        if (SKIP == 2) a += skip_b[co];
        if (RELU) a = fmaxf(a, 0.f);
        out[((b * COUT + co) * OH + oy) * OW + ox] = a;
    }
}

// ---------------------------------------------------------------------------
// XLA-style warp row reduction of sum(x*x) over 128 elements:
// lane-strided (lane, lane+32, lane+64, lane+96), sequential __fadd_rn of
// __fmul_rn squares, then shfl_down tree 16/8/4/2/1. Result in lane 0.
// ---------------------------------------------------------------------------
__device__ __forceinline__ float warp_sumsq_128(const float* __restrict__ x, int lane)
{
    float s = 0.f;
#pragma unroll
    for (int i = 0; i < 4; i++) {
        float v = x[lane + 32 * i];
        s = __fadd_rn(s, __fmul_rn(v, v));
    }
#pragma unroll
    for (int off = 16; off > 0; off >>= 1)
        s = __fadd_rn(s, __shfl_down_sync(0xffffffffu, s, off));
    return s;
}

// cnorm (one warp per code) + zero the loss accumulator.
__global__ void __launch_bounds__(256) prep_cnorm_k(const float* __restrict__ cb)
{
    if (blockIdx.x == 0 && threadIdx.x == 0) g_loss = 0.0;
    int warp = (blockIdx.x * 256 + threadIdx.x) >> 5;
    int lane = threadIdx.x & 31;
    if (warp < 1024) {
        float s = warp_sumsq_128(cb + warp * 128, lane);
        if (lane == 0) g_cnorm[warp] = s;
    }
}

// Transpose codebook into k-major layout for coalesced tiled reads.
__global__ void __launch_bounds__(256) transpose_cb_k(const float* __restrict__ cb)
{
    int i = blockIdx.x * 256 + threadIdx.x;   // 131072 elements
    int code = i >> 7, k = i & 127;
    g_cbT[k * 1024 + code] = cb[i];
}

// ---------------------------------------------------------------------------
// Quantizer: block = 256 threads handles 16 rows x all 1024 codes.
// Each thread owns codes [4t, 4t+3] as two f32x2 FMA chains per row.
// k strictly ascending, single accumulator per (row, code)  -> replicates a
// sequential-k fp32 GEMM. d uses the reference's exact fl() sequence.
// Writes straight-through fl(z + fl(q-z)) and accumulates sum((q-z)^2).
// ---------------------------------------------------------------------------
__global__ void __launch_bounds__(256) quantize_k(
    const float* __restrict__ z, const float* __restrict__ cb,
    float* __restrict__ qst)
{
    __shared__ float ct[8 * 1024];     // codebook tile: 8 k-slices x 1024 codes
    __shared__ float zs[16 * 128];     // 16 z rows
    __shared__ float znorm_s[16];
    __shared__ float cand_d[16][8];
    __shared__ int   cand_i[16][8];
    __shared__ int   kbest_s[16];
    __shared__ double red[256];

    const int t = threadIdx.x;
    const int lane = t & 31, w = t >> 5;
    const long long row0 = (long long)blockIdx.x * 16;

    // load 16 z rows to smem (bitwise copy)
    {
        const float4* zg = (const float4*)(z + row0 * 128);
        float4* z4 = (float4*)zs;
#pragma unroll
        for (int j = 0; j < 2; j++) z4[t + 256 * j] = zg[t + 256 * j];
    }
    __syncthreads();

    // znorm per row: warp w handles rows w and w+8
#pragma unroll
    for (int rr = 0; rr < 2; rr++) {
        int r = w + 8 * rr;
        float s = warp_sumsq_128(zs + r * 128, lane);
        if (lane == 0) znorm_s[r] = s;
    }

    ULL acc[16][2];
#pragma unroll
    for (int r = 0; r < 16; r++) { acc[r][0] = 0ull; acc[r][1] = 0ull; }

#pragma unroll 1
    for (int kt = 0; kt < 16; kt++) {
        __syncthreads();
        // stage 8 k-slices of transposed codebook (32 KB)
        {
            const float4* gt = (const float4*)(g_cbT + kt * 8 * 1024);
            float4* c4s = (float4*)ct;
#pragma unroll
            for (int j = 0; j < 8; j++) c4s[t + 256 * j] = gt[t + 256 * j];
        }
        __syncthreads();
#pragma unroll
        for (int kk = 0; kk < 8; kk++) {
            float4 c4 = ((const float4*)ct)[kk * 256 + t];   // codes 4t..4t+3 at k
            ULL cab = pack2(c4.x, c4.y);
            ULL ccd = pack2(c4.z, c4.w);
            const int k = kt * 8 + kk;
#pragma unroll
            for (int r = 0; r < 16; r++) {
                float zk = zs[r * 128 + k];
                ULL zz = pack2(zk, zk);
                acc[r][0] = fma2(zz, cab, acc[r][0]);
                acc[r][1] = fma2(zz, ccd, acc[r][1]);
            }
        }
    }
    __syncthreads();

    // d = fl( fl(znorm - 2*dot) + cnorm ), lexicographic argmin
    float4 cn4 = *(const float4*)(g_cnorm + 4 * t);
#pragma unroll
    for (int r = 0; r < 16; r++) {
        float a, b, c, d;
        unpack2(acc[r][0], a, b);
        unpack2(acc[r][1], c, d);
        float zn = znorm_s[r];
        float d0 = __fadd_rn(__fsub_rn(zn, __fmul_rn(2.f, a)), cn4.x);
        float d1 = __fadd_rn(__fsub_rn(zn, __fmul_rn(2.f, b)), cn4.y);
        float d2 = __fadd_rn(__fsub_rn(zn, __fmul_rn(2.f, c)), cn4.z);
        float d3 = __fadd_rn(__fsub_rn(zn, __fmul_rn(2.f, d)), cn4.w);
        float bv = d0; int bi = 4 * t;
        if (d1 < bv) { bv = d1; bi = 4 * t + 1; }
        if (d2 < bv) { bv = d2; bi = 4 * t + 2; }
        if (d3 < bv) { bv = d3; bi = 4 * t + 3; }
#pragma unroll
        for (int off = 16; off > 0; off >>= 1) {
            float ov = __shfl_down_sync(0xffffffffu, bv, off);
            int   oi = __shfl_down_sync(0xffffffffu, bi, off);
            if (ov < bv || (ov == bv && oi < bi)) { bv = ov; bi = oi; }
        }
        if (lane == 0) { cand_d[r][w] = bv; cand_i[r][w] = bi; }
    }
    __syncthreads();
    if (t < 16) {
        float bv = cand_d[t][0]; int bi = cand_i[t][0];
#pragma unroll
        for (int j = 1; j < 8; j++) {
            float ov = cand_d[t][j]; int oi = cand_i[t][j];
            if (ov < bv || (ov == bv && oi < bi)) { bv = ov; bi = oi; }
        }
        kbest_s[t] = bi;
    }
    __syncthreads();

    // straight-through output + loss partials
    double ls = 0.0;
#pragma unroll
    for (int j = 0; j < 8; j++) {
        int e = j * 256 + t;
        int r = e >> 7, col = e & 127;
        float zv = zs[r * 128 + col];
        float qv = cb[kbest_s[r] * 128 + col];
        float qz = __fsub_rn(qv, zv);                // fl(q - z)
        float st = __fadd_rn(zv, qz);                // fl(z + fl(q - z))
        qst[(row0 + r) * 128 + col] = st;
        ls += (double)qz * (double)qz;
    }
    red[t] = ls;
    __syncthreads();
    for (int s = 128; s > 0; s >>= 1) {
        if (t < s) red[t] += red[t + s];
        __syncthreads();
    }
    if (t == 0) atomicAdd(&g_loss, red[0]);
}

// Write loss (= 1.25 * mean((q-z)^2)) into the tail of the output buffer.
__global__ void finish_k(float* __restrict__ out, int start, int total)
{
    float v = (float)(1.25 * g_loss / 16777216.0);
    for (int i = start + threadIdx.x; i < total; i += 32) out[i] = v;
}

// ---------------------------------------------------------------------------
extern "C" void kernel_launch(void* const* d_in, const int* in_sizes, int n_in,
                              void* d_out, int out_size)
{
    const float* x          = (const float*)d_in[0];
    const float* enc_in_w   = (const float*)d_in[1];
    const float* enc_in_b   = (const float*)d_in[2];
    const float* rb0_w1     = (const float*)d_in[3];
    const float* rb0_b1     = (const float*)d_in[4];
    const float* rb0_w2     = (const float*)d_in[5];
    const float* rb0_b2     = (const float*)d_in[6];
    const float* rb1_w1     = (const float*)d_in[7];
    const float* rb1_b1     = (const float*)d_in[8];
    const float* rb1_w2     = (const float*)d_in[9];
    const float* rb1_b2     = (const float*)d_in[10];
    const float* rb1_ws     = (const float*)d_in[11];
    const float* rb1_bs     = (const float*)d_in[12];
    const float* down_w     = (const float*)d_in[13];
    const float* down_b     = (const float*)d_in[14];
    const float* codebook   = (const float*)d_in[15];
    const float* d1_w1      = (const float*)d_in[16];
    const float* d1_b1      = (const float*)d_in[17];
    const float* d1_w2      = (const float*)d_in[18];
    const float* d1_b2      = (const float*)d_in[19];
    const float* up_w       = (const float*)d_in[20];
    const float* up_b       = (const float*)d_in[21];
    const float* d0_w1      = (const float*)d_in[22];
    const float* d0_b1      = (const float*)d_in[23];
    const float* d0_w2      = (const float*)d_in[24];
    const float* d0_b2      = (const float*)d_in[25];
    const float* out_w      = (const float*)d_in[26];
    const float* out_b      = (const float*)d_in[27];
    float* out = (float*)d_out;

    float *bufA, *bufB, *bufC;
    cudaGetSymbolAddress((void**)&bufA, g_bufA);
    cudaGetSymbolAddress((void**)&bufB, g_bufB);
    cudaGetSymbolAddress((void**)&bufC, g_bufC);

    const int B = 8;
    dim3 blk(16, 16);
    dim3 g256_64(16, 16, B * 4);
    dim3 g256_128(16, 16, B * 8);
    dim3 g128_128(8, 8, B * 8);
    dim3 g256_3(16, 16, B * 1);

    // quantizer prep (independent of encoder; launch early)
    transpose_cb_k<<<512, 256>>>(codebook);
    prep_cnorm_k<<<128, 256>>>(codebook);

    // ---- encoder ----
    conv3x3_k<3, 16, 1, false, 0, false><<<g256_64, blk>>>(
        x, enc_in_w, enc_in_b, nullptr, nullptr, nullptr, bufA,
        256, 256, 256, 256, 64, 0, 4);
    conv3x3_k<64, 16, 1, true, 0, false><<<g256_64, blk>>>(
        bufA, rb0_w1, rb0_b1, nullptr, nullptr, nullptr, bufB,
        256, 256, 256, 256, 64, 0, 4);
    conv3x3_k<64, 16, 1, true, 1, false><<<g256_64, blk>>>(
        bufB, rb0_w2, rb0_b2, bufA, nullptr, nullptr, bufC,
        256, 256, 256, 256, 64, 0, 4);
    conv3x3_k<64, 16, 1, true, 0, false><<<g256_128, blk>>>(
        bufC, rb1_w1, rb1_b1, nullptr, nullptr, nullptr, bufA,
        256, 256, 256, 256, 128, 0, 8);
    conv3x3_k<128, 16, 1, true, 2, false><<<g256_128, blk>>>(
        bufA, rb1_w2, rb1_b2, bufC, rb1_ws, rb1_bs, bufB,
        256, 256, 256, 256, 128, 64, 8);
    conv3x3_k<128, 16, 2, true, 0, false><<<g128_128, blk>>>(
        bufB, down_w, down_b, nullptr, nullptr, nullptr, bufC,
        256, 256, 128, 128, 128, 0, 8);

    // ---- quantizer ----
    quantize_k<<<8192, 256>>>(bufC, codebook, bufA);   // q_st -> bufA

    // ---- decoder ----
    conv3x3_k<128, 16, 1, true, 0, false><<<g128_128, blk>>>(
        bufA, d1_w1, d1_b1, nullptr, nullptr, nullptr, bufB,
        128, 128, 128, 128, 128, 0, 8);
    conv3x3_k<128, 16, 1, true, 1, false><<<g128_128, blk>>>(
        bufB, d1_w2, d1_b2, bufA, nullptr, nullptr, bufC,
        128, 128, 128, 128, 128, 0, 8);
    conv3x3_k<128, 16, 1, true, 0, true><<<g256_64, blk>>>(
        bufC, up_w, up_b, nullptr, nullptr, nullptr, bufA,
        128, 128, 256, 256, 64, 0, 4);
    conv3x3_k<64, 16, 1, true, 0, false><<<g256_64, blk>>>(
        bufA, d0_w1, d0_b1, nullptr, nullptr, nullptr, bufB,
        256, 256, 256, 256, 64, 0, 4);
    conv3x3_k<64, 16, 1, true, 1, false><<<g256_64, blk>>>(
        bufB, d0_w2, d0_b2, bufA, nullptr, nullptr, bufC,
        256, 256, 256, 256, 64, 0, 4);
    conv3x3_k<64, 4, 1, false, 0, false><<<g256_3, blk>>>(
        bufC, out_w, out_b, nullptr, nullptr, nullptr, out,
        256, 256, 256, 256, 3, 0, 1);

    const int recon = 8 * 3 * 256 * 256;
    if (out_size > recon) finish_k<<<1, 32>>>(out, recon, out_size);
}

// round 5
// speedup vs baseline: 1.2195x; 1.2195x over previous
#include <cuda_runtime.h>
#include <cuda_bf16.h>

// ---------------------------------------------------------------------------
// VQ-VAE forward on GB300 (sm_103a).
// R5: register-tiled direct conv (2x4 px * 8 outch per thread, f32x2 FMA),
// weights/tile read via LDS.128 -> FMA-pipe bound instead of L1-bound.
// Quantizer arithmetic unchanged from R4 (bit-replicates reference).
// ---------------------------------------------------------------------------

#define ULL unsigned long long

__device__ __forceinline__ ULL pack2(float a, float b) {
    ULL r; asm("mov.b64 %0, {%1, %2};" : "=l"(r) : "f"(a), "f"(b)); return r;
}
__device__ __forceinline__ void unpack2(ULL v, float& a, float& b) {
    asm("mov.b64 {%0, %1}, %2;" : "=f"(a), "=f"(b) : "l"(v));
}
__device__ __forceinline__ ULL fma2(ULL a, ULL b, ULL c) {
    ULL d; asm("fma.rn.f32x2 %0, %1, %2, %3;" : "=l"(d) : "l"(a), "l"(b), "l"(c)); return d;
}

// Scratch buffers (max tensor: 8 x 128 x 256 x 256 fp32 = 256 MB each)
__device__ float g_bufA[8 * 128 * 256 * 256];
__device__ float g_bufB[8 * 128 * 256 * 256];
__device__ float g_bufC[8 * 128 * 256 * 256];
__device__ float g_cbT[128 * 1024];   // codebook transposed: [k][code]
__device__ float g_cnorm[1024];
__device__ double g_loss;

// ---------------------------------------------------------------------------
// NEW register-tiled conv (stride 1 only).
// Block: 256 threads -> output tile 64(w) x 32(h), 8 output channels (co0..+7).
// Thread (tx=t&15, ty=t>>4) computes pixels (oy0+py, ox0+px), py<2, px<4,
// as 32 f32x2 accumulators. Weights & input patch read via vector LDS.
// SKIP: 0 none, 1 identity add, 2 fused 1x1-conv skip. UPS: nearest-2x input.
// ---------------------------------------------------------------------------
template <int CIN, bool RELU, int SKIP, bool UPS>
__global__ void __launch_bounds__(256, 2) conv3x3n_k(
    const float* __restrict__ in, const float* __restrict__ wgt,
    const float* __restrict__ bias,
    const float* __restrict__ skip_in, const float* __restrict__ skip_w,
    const float* __restrict__ skip_b,
    float* __restrict__ out,
    int IH, int IW, int OH, int OW, int COUT, int CSKIP, int nG)
{
    __shared__ __align__(16) float tile[34 * 68];
    __shared__ __align__(16) ULL ws2[9 * 4];

    const int t = threadIdx.x;
    const int tx = t & 15, ty = t >> 4;
    const int b = blockIdx.z / nG;
    const int co0 = (blockIdx.z - b * nG) * 8;
    const int ox0 = blockIdx.x * 64 + 4 * tx;
    const int oy0 = blockIdx.y * 32 + 2 * ty;
    const int x0 = blockIdx.x * 64 - 1;
    const int y0 = blockIdx.y * 32 - 1;
    const int DH = UPS ? IH * 2 : IH;
    const int DW = UPS ? IW * 2 : IW;

    ULL acc[2][4][4];
#pragma unroll
    for (int py = 0; py < 2; py++)
#pragma unroll
        for (int px = 0; px < 4; px++)
#pragma unroll
            for (int p = 0; p < 4; p++) acc[py][px][p] = 0ull;

#pragma unroll 1
    for (int ci = 0; ci < CIN; ci++) {
        const float* inc = in + (b * CIN + ci) * IH * IW;
        // stage 34x66 input tile (row stride padded to 68 for aligned LDS.128)
        for (int i = t; i < 34 * 68; i += 256) {
            int row = i / 68, col = i - row * 68;
            int gy = y0 + row, gx = x0 + col;
            float v = 0.f;
            if (col < 66 && (unsigned)gy < (unsigned)DH && (unsigned)gx < (unsigned)DW) {
                int iy = UPS ? (gy >> 1) : gy;
                int ix = UPS ? (gx >> 1) : gx;
                v = inc[iy * IW + ix];
            }
            tile[i] = v;
        }
        // stage packed weight pairs: ws2[k*4+p] = (w[co0+2p], w[co0+2p+1]) at tap k
        if (t < 36) {
            int k = t >> 2, p = t & 3;
            int ca = co0 + 2 * p;
            float wa = (ca < COUT) ? wgt[(ca * CIN + ci) * 9 + k] : 0.f;
            float wb = (ca + 1 < COUT) ? wgt[((ca + 1) * CIN + ci) * 9 + k] : 0.f;
            ws2[t] = pack2(wa, wb);
        }
        __syncthreads();

        // 4x6 input patch into registers (float4 + float2 per row)
        float rv[4][6];
#pragma unroll
        for (int r = 0; r < 4; r++) {
            const float* p = &tile[(2 * ty + r) * 68 + 4 * tx];
            float4 a = *(const float4*)p;
            float2 b2 = *(const float2*)(p + 4);
            rv[r][0] = a.x; rv[r][1] = a.y; rv[r][2] = a.z; rv[r][3] = a.w;
            rv[r][4] = b2.x; rv[r][5] = b2.y;
        }

#pragma unroll
        for (int ky = 0; ky < 3; ky++) {
#pragma unroll
            for (int kx = 0; kx < 3; kx++) {
                const int k = ky * 3 + kx;
                ulonglong2 wA = ((const ulonglong2*)ws2)[k * 2];
                ulonglong2 wB = ((const ulonglong2*)ws2)[k * 2 + 1];
#pragma unroll
                for (int py = 0; py < 2; py++) {
#pragma unroll
                    for (int px = 0; px < 4; px++) {
                        float v = rv[py + ky][px + kx];
                        ULL vv = pack2(v, v);
                        acc[py][px][0] = fma2(vv, wA.x, acc[py][px][0]);
                        acc[py][px][1] = fma2(vv, wA.y, acc[py][px][1]);
                        acc[py][px][2] = fma2(vv, wB.x, acc[py][px][2]);
                        acc[py][px][3] = fma2(vv, wB.y, acc[py][px][3]);
                    }
                }
            }
        }
        __syncthreads();
    }

    // fused 1x1-conv skip: accumulate into the same f32x2 chains
    if (SKIP == 2) {
#pragma unroll 1
        for (int cs = 0; cs < CSKIP; cs++) {
            for (int i = t; i < 32 * 64; i += 256) {
                int row = i >> 6, col = i & 63;
                tile[i] = skip_in[((b * CSKIP + cs) * OH + blockIdx.y * 32 + row) * OW
                                  + blockIdx.x * 64 + col];
            }
            if (t < 4) {
                int ca = co0 + 2 * t;
                float wa = (ca < COUT) ? skip_w[ca * CSKIP + cs] : 0.f;
                float wb = (ca + 1 < COUT) ? skip_w[(ca + 1) * CSKIP + cs] : 0.f;
                ws2[t] = pack2(wa, wb);
            }
            __syncthreads();
            ulonglong2 wA = ((const ulonglong2*)ws2)[0];
            ulonglong2 wB = ((const ulonglong2*)ws2)[1];
#pragma unroll
            for (int py = 0; py < 2; py++) {
                float4 s4 = *(const float4*)&tile[(2 * ty + py) * 64 + 4 * tx];
                float sv[4] = {s4.x, s4.y, s4.z, s4.w};
#pragma unroll
                for (int px = 0; px < 4; px++) {
                    ULL vv = pack2(sv[px], sv[px]);
                    acc[py][px][0] = fma2(vv, wA.x, acc[py][px][0]);
                    acc[py][px][1] = fma2(vv, wA.y, acc[py][px][1]);
                    acc[py][px][2] = fma2(vv, wB.x, acc[py][px][2]);
                    acc[py][px][3] = fma2(vv, wB.y, acc[py][px][3]);
                }
            }
            __syncthreads();
        }
    }

    // epilogue: bias (+skip) (+relu), float4 stores
    float bv[8];
#pragma unroll
    for (int c = 0; c < 8; c++) bv[c] = (co0 + c < COUT) ? bias[co0 + c] : 0.f;

#pragma unroll
    for (int c = 0; c < 8; c++) {
        const int co = co0 + c;
        if (co < COUT) {
            const int p = c >> 1, hi = c & 1;
#pragma unroll
            for (int py = 0; py < 2; py++) {
                float o[4];
#pragma unroll
                for (int px = 0; px < 4; px++) {
                    float a0, a1;
                    unpack2(acc[py][px][p], a0, a1);
                    o[px] = (hi ? a1 : a0) + bv[c];
                }
                const int base = ((b * COUT + co) * OH + oy0 + py) * OW + ox0;
                if (SKIP == 1) {
                    float4 s = *(const float4*)&skip_in[base];
                    o[0] += s.x; o[1] += s.y; o[2] += s.z; o[3] += s.w;
                }
                if (SKIP == 2) {
                    float sb = skip_b[co];
#pragma unroll
                    for (int px = 0; px < 4; px++) o[px] += sb;
                }
                if (RELU) {
#pragma unroll
                    for (int px = 0; px < 4; px++) o[px] = fmaxf(o[px], 0.f);
                }
                float4 ov; ov.x = o[0]; ov.y = o[1]; ov.z = o[2]; ov.w = o[3];
                *(float4*)&out[base] = ov;
            }
        }
    }
}

// ---------------------------------------------------------------------------
// OLD direct conv — retained for the stride-2 downsample layer only.
// ---------------------------------------------------------------------------
template <int CIN, int OUTC, int STRIDE, bool RELU, int SKIP, bool UPS>
__global__ void __launch_bounds__(256) conv3x3_k(
    const float* __restrict__ in, const float* __restrict__ wgt,
    const float* __restrict__ bias,
    const float* __restrict__ skip_in, const float* __restrict__ skip_w,
    const float* __restrict__ skip_b,
    float* __restrict__ out,
    int IH, int IW, int OH, int OW, int COUT, int CSKIP, int nG)
{
    constexpr int TS = 16 * STRIDE + 2;
    constexpr int NP = OUTC / 2;
    __shared__ float tile[TS * TS];
    __shared__ ULL ws2[9 * NP];

    const int tx = threadIdx.x, ty = threadIdx.y;
    const int tid = ty * 16 + tx;
    const int bz = blockIdx.z;
    const int b = bz / nG;
    const int co0 = (bz - b * nG) * OUTC;
    const int oy = blockIdx.y * 16 + ty;
    const int ox = blockIdx.x * 16 + tx;
    const int y0 = blockIdx.y * 16 * STRIDE - 1;
    const int x0 = blockIdx.x * 16 * STRIDE - 1;
    const int DH = UPS ? IH * 2 : IH;
    const int DW = UPS ? IW * 2 : IW;

    ULL acc[NP];
#pragma unroll
    for (int p = 0; p < NP; p++) acc[p] = 0ull;

#pragma unroll 1
    for (int ci = 0; ci < CIN; ci++) {
        const float* inc = in + (b * CIN + ci) * IH * IW;
        for (int i = tid; i < TS * TS; i += 256) {
            int sy = i / TS, sx = i - sy * TS;
            int gy = y0 + sy, gx = x0 + sx;
            float v = 0.f;
            if ((unsigned)gy < (unsigned)DH && (unsigned)gx < (unsigned)DW) {
                int iy = UPS ? (gy >> 1) : gy;
                int ix = UPS ? (gx >> 1) : gx;
                v = inc[iy * IW + ix];
            }
            tile[i] = v;
        }
        if (tid < 9 * NP) {
            int k = tid / NP, p = tid - k * NP;
            int ca = co0 + 2 * p;
            float wa = (ca < COUT) ? wgt[(ca * CIN + ci) * 9 + k] : 0.f;
            float wb = (ca + 1 < COUT) ? wgt[((ca + 1) * CIN + ci) * 9 + k] : 0.f;
            ws2[tid] = pack2(wa, wb);
        }
        __syncthreads();

#pragma unroll
        for (int ky = 0; ky < 3; ky++) {
#pragma unroll
            for (int kx = 0; kx < 3; kx++) {
                float v = tile[(ty * STRIDE + ky) * TS + tx * STRIDE + kx];
                ULL vv = pack2(v, v);
                const ULL* wrow = &ws2[(ky * 3 + kx) * NP];
#pragma unroll
                for (int p = 0; p < NP; p++) acc[p] = fma2(vv, wrow[p], acc[p]);
            }
        }
        __syncthreads();
    }

    float accf[OUTC];
#pragma unroll
    for (int p = 0; p < NP; p++) unpack2(acc[p], accf[2 * p], accf[2 * p + 1]);

#pragma unroll
    for (int c = 0; c < OUTC; c++) {
        int co = co0 + c;
        if (co >= COUT) break;
        float a = accf[c] + bias[co];
        if (RELU) a = fmaxf(a, 0.f);
        out[((b * COUT + co) * OH + oy) * OW + ox] = a;
    }
}

// ---------------------------------------------------------------------------
// XLA-style warp row reduction of sum(x*x) over 128 elements.
// ---------------------------------------------------------------------------
__device__ __forceinline__ float warp_sumsq_128(const float* __restrict__ x, int lane)
{
    float s = 0.f;
#pragma unroll
    for (int i = 0; i < 4; i++) {
        float v = x[lane + 32 * i];
        s = __fadd_rn(s, __fmul_rn(v, v));
    }
#pragma unroll
    for (int off = 16; off > 0; off >>= 1)
        s = __fadd_rn(s, __shfl_down_sync(0xffffffffu, s, off));
    return s;
}

__global__ void __launch_bounds__(256) prep_cnorm_k(const float* __restrict__ cb)
{
    if (blockIdx.x == 0 && threadIdx.x == 0) g_loss = 0.0;
    int warp = (blockIdx.x * 256 + threadIdx.x) >> 5;
    int lane = threadIdx.x & 31;
    if (warp < 1024) {
        float s = warp_sumsq_128(cb + warp * 128, lane);
        if (lane == 0) g_cnorm[warp] = s;
    }
}

__global__ void __launch_bounds__(256) transpose_cb_k(const float* __restrict__ cb)
{
    int i = blockIdx.x * 256 + threadIdx.x;
    int code = i >> 7, k = i & 127;
    g_cbT[k * 1024 + code] = cb[i];
}

// ---------------------------------------------------------------------------
// Quantizer (unchanged from R4 — arithmetic is load-bearing):
// d = fl( fl(znorm - 2*dot) + cnorm ), sequential-k fp32 FMA chains,
// lexicographic argmin, straight-through fl(z + fl(q - z)).
// ---------------------------------------------------------------------------
__global__ void __launch_bounds__(256) quantize_k(
    const float* __restrict__ z, const float* __restrict__ cb,
    float* __restrict__ qst)
{
    __shared__ float ct[8 * 1024];
    __shared__ float zs[16 * 128];
    __shared__ float znorm_s[16];
    __shared__ float cand_d[16][8];
    __shared__ int   cand_i[16][8];
    __shared__ int   kbest_s[16];
    __shared__ double red[256];

    const int t = threadIdx.x;
    const int lane = t & 31, w = t >> 5;
    const long long row0 = (long long)blockIdx.x * 16;

    {
        const float4* zg = (const float4*)(z + row0 * 128);
        float4* z4 = (float4*)zs;
#pragma unroll
        for (int j = 0; j < 2; j++) z4[t + 256 * j] = zg[t + 256 * j];
    }
    __syncthreads();

#pragma unroll
    for (int rr = 0; rr < 2; rr++) {
        int r = w + 8 * rr;
        float s = warp_sumsq_128(zs + r * 128, lane);
        if (lane == 0) znorm_s[r] = s;
    }

    ULL acc[16][2];
#pragma unroll
    for (int r = 0; r < 16; r++) { acc[r][0] = 0ull; acc[r][1] = 0ull; }

#pragma unroll 1
    for (int kt = 0; kt < 16; kt++) {
        __syncthreads();
        {
            const float4* gt = (const float4*)(g_cbT + kt * 8 * 1024);
            float4* c4s = (float4*)ct;
#pragma unroll
            for (int j = 0; j < 8; j++) c4s[t + 256 * j] = gt[t + 256 * j];
        }
        __syncthreads();
#pragma unroll
        for (int kk = 0; kk < 8; kk++) {
            float4 c4 = ((const float4*)ct)[kk * 256 + t];
            ULL cab = pack2(c4.x, c4.y);
            ULL ccd = pack2(c4.z, c4.w);
            const int k = kt * 8 + kk;
#pragma unroll
            for (int r = 0; r < 16; r++) {
                float zk = zs[r * 128 + k];
                ULL zz = pack2(zk, zk);
                acc[r][0] = fma2(zz, cab, acc[r][0]);
                acc[r][1] = fma2(zz, ccd, acc[r][1]);
            }
        }
    }
    __syncthreads();

    float4 cn4 = *(const float4*)(g_cnorm + 4 * t);
#pragma unroll
    for (int r = 0; r < 16; r++) {
        float a, b, c, d;
        unpack2(acc[r][0], a, b);
        unpack2(acc[r][1], c, d);
        float zn = znorm_s[r];
        float d0 = __fadd_rn(__fsub_rn(zn, __fmul_rn(2.f, a)), cn4.x);
        float d1 = __fadd_rn(__fsub_rn(zn, __fmul_rn(2.f, b)), cn4.y);
        float d2 = __fadd_rn(__fsub_rn(zn, __fmul_rn(2.f, c)), cn4.z);
        float d3 = __fadd_rn(__fsub_rn(zn, __fmul_rn(2.f, d)), cn4.w);
        float bv = d0; int bi = 4 * t;
        if (d1 < bv) { bv = d1; bi = 4 * t + 1; }
        if (d2 < bv) { bv = d2; bi = 4 * t + 2; }
        if (d3 < bv) { bv = d3; bi = 4 * t + 3; }
#pragma unroll
        for (int off = 16; off > 0; off >>= 1) {
            float ov = __shfl_down_sync(0xffffffffu, bv, off);
            int   oi = __shfl_down_sync(0xffffffffu, bi, off);
            if (ov < bv || (ov == bv && oi < bi)) { bv = ov; bi = oi; }
        }
        if (lane == 0) { cand_d[r][w] = bv; cand_i[r][w] = bi; }
    }
    __syncthreads();
    if (t < 16) {
        float bv = cand_d[t][0]; int bi = cand_i[t][0];
#pragma unroll
        for (int j = 1; j < 8; j++) {
            float ov = cand_d[t][j]; int oi = cand_i[t][j];
            if (ov < bv || (ov == bv && oi < bi)) { bv = ov; bi = oi; }
        }
        kbest_s[t] = bi;
    }
    __syncthreads();

    double ls = 0.0;
#pragma unroll
    for (int j = 0; j < 8; j++) {
        int e = j * 256 + t;
        int r = e >> 7, col = e & 127;
        float zv = zs[r * 128 + col];
        float qv = cb[kbest_s[r] * 128 + col];
        float qz = __fsub_rn(qv, zv);
        float st = __fadd_rn(zv, qz);
        qst[(row0 + r) * 128 + col] = st;
        ls += (double)qz * (double)qz;
    }
    red[t] = ls;
    __syncthreads();
    for (int s = 128; s > 0; s >>= 1) {
        if (t < s) red[t] += red[t + s];
        __syncthreads();
    }
    if (t == 0) atomicAdd(&g_loss, red[0]);
}

__global__ void finish_k(float* __restrict__ out, int start, int total)
{
    float v = (float)(1.25 * g_loss / 16777216.0);
    for (int i = start + threadIdx.x; i < total; i += 32) out[i] = v;
}

// ---------------------------------------------------------------------------
extern "C" void kernel_launch(void* const* d_in, const int* in_sizes, int n_in,
                              void* d_out, int out_size)
{
    const float* x          = (const float*)d_in[0];
    const float* enc_in_w   = (const float*)d_in[1];
    const float* enc_in_b   = (const float*)d_in[2];
    const float* rb0_w1     = (const float*)d_in[3];
    const float* rb0_b1     = (const float*)d_in[4];
    const float* rb0_w2     = (const float*)d_in[5];
    const float* rb0_b2     = (const float*)d_in[6];
    const float* rb1_w1     = (const float*)d_in[7];
    const float* rb1_b1     = (const float*)d_in[8];
    const float* rb1_w2     = (const float*)d_in[9];
    const float* rb1_b2     = (const float*)d_in[10];
    const float* rb1_ws     = (const float*)d_in[11];
    const float* rb1_bs     = (const float*)d_in[12];
    const float* down_w     = (const float*)d_in[13];
    const float* down_b     = (const float*)d_in[14];
    const float* codebook   = (const float*)d_in[15];
    const float* d1_w1      = (const float*)d_in[16];
    const float* d1_b1      = (const float*)d_in[17];
    const float* d1_w2      = (const float*)d_in[18];
    const float* d1_b2      = (const float*)d_in[19];
    const float* up_w       = (const float*)d_in[20];
    const float* up_b       = (const float*)d_in[21];
    const float* d0_w1      = (const float*)d_in[22];
    const float* d0_b1      = (const float*)d_in[23];
    const float* d0_w2      = (const float*)d_in[24];
    const float* d0_b2      = (const float*)d_in[25];
    const float* out_w      = (const float*)d_in[26];
    const float* out_b      = (const float*)d_in[27];
    float* out = (float*)d_out;

    float *bufA, *bufB, *bufC;
    cudaGetSymbolAddress((void**)&bufA, g_bufA);
    cudaGetSymbolAddress((void**)&bufB, g_bufB);
    cudaGetSymbolAddress((void**)&bufC, g_bufC);

    const int B = 8;
    // new kernel grids: tile 64x32
    dim3 G256_64(4, 8, B * 8);     // 256x256, 64 outch (8 groups)
    dim3 G256_128(4, 8, B * 16);   // 256x256, 128 outch (16 groups)
    dim3 G128_128(2, 4, B * 16);   // 128x128, 128 outch
    dim3 G256_3(4, 8, B * 1);      // 256x256, 3 outch
    dim3 blk_old(16, 16);
    dim3 g128_old(8, 8, B * 8);    // old kernel for stride-2

    // quantizer prep (independent of encoder)
    transpose_cb_k<<<512, 256>>>(codebook);
    prep_cnorm_k<<<128, 256>>>(codebook);

    // ---- encoder ----
    conv3x3n_k<3, false, 0, false><<<G256_64, 256>>>(
        x, enc_in_w, enc_in_b, nullptr, nullptr, nullptr, bufA,
        256, 256, 256, 256, 64, 0, 8);
    conv3x3n_k<64, true, 0, false><<<G256_64, 256>>>(
        bufA, rb0_w1, rb0_b1, nullptr, nullptr, nullptr, bufB,
        256, 256, 256, 256, 64, 0, 8);
    conv3x3n_k<64, true, 1, false><<<G256_64, 256>>>(
        bufB, rb0_w2, rb0_b2, bufA, nullptr, nullptr, bufC,
        256, 256, 256, 256, 64, 0, 8);
    conv3x3n_k<64, true, 0, false><<<G256_128, 256>>>(
        bufC, rb1_w1, rb1_b1, nullptr, nullptr, nullptr, bufA,
        256, 256, 256, 256, 128, 0, 16);
    conv3x3n_k<128, true, 2, false><<<G256_128, 256>>>(
        bufA, rb1_w2, rb1_b2, bufC, rb1_ws, rb1_bs, bufB,
        256, 256, 256, 256, 128, 64, 16);
    conv3x3_k<128, 16, 2, true, 0, false><<<g128_old, blk_old>>>(
        bufB, down_w, down_b, nullptr, nullptr, nullptr, bufC,
        256, 256, 128, 128, 128, 0, 8);

    // ---- quantizer ----
    quantize_k<<<8192, 256>>>(bufC, codebook, bufA);   // q_st -> bufA

    // ---- decoder ----
    conv3x3n_k<128, true, 0, false><<<G128_128, 256>>>(
        bufA, d1_w1, d1_b1, nullptr, nullptr, nullptr, bufB,
        128, 128, 128, 128, 128, 0, 16);
    conv3x3n_k<128, true, 1, false><<<G128_128, 256>>>(
        bufB, d1_w2, d1_b2, bufA, nullptr, nullptr, bufC,
        128, 128, 128, 128, 128, 0, 16);
    conv3x3n_k<128, true, 0, true><<<G256_64, 256>>>(
        bufC, up_w, up_b, nullptr, nullptr, nullptr, bufA,
        128, 128, 256, 256, 64, 0, 8);
    conv3x3n_k<64, true, 0, false><<<G256_64, 256>>>(
        bufA, d0_w1, d0_b1, nullptr, nullptr, nullptr, bufB,
        256, 256, 256, 256, 64, 0, 8);
    conv3x3n_k<64, true, 1, false><<<G256_64, 256>>>(
        bufB, d0_w2, d0_b2, bufA, nullptr, nullptr, bufC,
        256, 256, 256, 256, 64, 0, 8);
    conv3x3n_k<64, false, 0, false><<<G256_3, 256>>>(
        bufC, out_w, out_b, nullptr, nullptr, nullptr, out,
        256, 256, 256, 256, 3, 0, 1);

    const int recon = 8 * 3 * 256 * 256;
    if (out_size > recon) finish_k<<<1, 32>>>(out, recon, out_size);
}

// round 6
// speedup vs baseline: 1.6210x; 1.3292x over previous
#include <cuda_runtime.h>
#include <cuda_bf16.h>

// ---------------------------------------------------------------------------
// VQ-VAE forward on GB300 (sm_103a).
// R6: register-tiled direct conv (2x4 px * 8 outch per thread, f32x2 FMA)
// with CI-BATCHED staging (4 input channels per sync round, division-free
// indexing) -> fewer syncs + batched LDGs hide memory latency.
// Quantizer arithmetic unchanged (bit-replicates reference).
// ---------------------------------------------------------------------------

#define ULL unsigned long long

__device__ __forceinline__ ULL pack2(float a, float b) {
    ULL r; asm("mov.b64 %0, {%1, %2};" : "=l"(r) : "f"(a), "f"(b)); return r;
}
__device__ __forceinline__ void unpack2(ULL v, float& a, float& b) {
    asm("mov.b64 {%0, %1}, %2;" : "=f"(a), "=f"(b) : "l"(v));
}
__device__ __forceinline__ ULL fma2(ULL a, ULL b, ULL c) {
    ULL d; asm("fma.rn.f32x2 %0, %1, %2, %3;" : "=l"(d) : "l"(a), "l"(b), "l"(c)); return d;
}

// Scratch buffers (max tensor: 8 x 128 x 256 x 256 fp32 = 256 MB each)
__device__ float g_bufA[8 * 128 * 256 * 256];
__device__ float g_bufB[8 * 128 * 256 * 256];
__device__ float g_bufC[8 * 128 * 256 * 256];
__device__ float g_cbT[128 * 1024];   // codebook transposed: [k][code]
__device__ float g_cnorm[1024];
__device__ double g_loss;

// ---------------------------------------------------------------------------
// Register-tiled conv, stride 1. Block: 256 threads -> 64(w) x 32(h) tile,
// 8 output channels. Thread (tx,ty) computes 2x4 pixels as 32 f32x2 accs
// (pairs over output channels). CIB input channels staged per sync round.
// SKIP: 0 none, 1 identity add, 2 fused 1x1-conv skip. UPS: nearest-2x input.
// ---------------------------------------------------------------------------
template <int CIN, int CIB, bool RELU, int SKIP, bool UPS>
__global__ void __launch_bounds__(256, 2) conv3x3n_k(
    const float* __restrict__ in, const float* __restrict__ wgt,
    const float* __restrict__ bias,
    const float* __restrict__ skip_in, const float* __restrict__ skip_w,
    const float* __restrict__ skip_b,
    float* __restrict__ out,
    int IH, int IW, int OH, int OW, int COUT, int CSKIP, int nG)
{
    __shared__ __align__(16) float tile[CIB * 34 * 68];
    __shared__ __align__(16) ULL ws2[CIB * 36];

    const int t = threadIdx.x;
    const int tx = t & 15, ty = t >> 4;
    const int b = blockIdx.z / nG;
    const int co0 = (blockIdx.z - b * nG) * 8;
    const int ox0 = blockIdx.x * 64 + 4 * tx;
    const int oy0 = blockIdx.y * 32 + 2 * ty;
    const int x0 = blockIdx.x * 64 - 1;
    const int y0 = blockIdx.y * 32 - 1;
    const int DH = UPS ? IH * 2 : IH;
    const int DW = UPS ? IW * 2 : IW;

    // ---- hoisted staging coordinates (division-free) ----
    // main: thread covers col tc for rows tr, tr+4, ..., tr+32
    const int tr = t >> 6;          // 0..3
    const int tc = t & 63;          // 0..63
    const int gx_m = x0 + tc;
    const bool vx_m = (unsigned)gx_m < (unsigned)DW;
    const int ix_m = UPS ? (gx_m >> 1) : gx_m;
    // tail: cols 64..67, rows 0..33 handled by threads t < 136
    const int trow_t = t >> 2;
    const int gx_t = x0 + 64 + (t & 3);
    const bool vx_t = (unsigned)gx_t < (unsigned)DW;
    const int ix_t = UPS ? (gx_t >> 1) : gx_t;

    ULL acc[2][4][4];
#pragma unroll
    for (int py = 0; py < 2; py++)
#pragma unroll
        for (int px = 0; px < 4; px++)
#pragma unroll
            for (int p = 0; p < 4; p++) acc[py][px][p] = 0ull;

#pragma unroll 1
    for (int ci0 = 0; ci0 < CIN; ci0 += CIB) {
        // ---- stage CIB weight slices: ws2[ci_l*36 + k*4 + p] = (w2p, w2p+1)
        if (t < CIB * 36) {
            int ci_l = t / 36, r = t - ci_l * 36;
            int k = r >> 2, p = r & 3;
            int ca = co0 + 2 * p;
            int ci = ci0 + ci_l;
            float wa = (ca < COUT) ? wgt[(ca * CIN + ci) * 9 + k] : 0.f;
            float wb = (ca + 1 < COUT) ? wgt[((ca + 1) * CIN + ci) * 9 + k] : 0.f;
            ws2[ci_l * 36 + k * 4 + p] = pack2(wa, wb);
        }
        // ---- stage CIB input tiles (34 rows x 66 cols, padded stride 68)
#pragma unroll
        for (int ci_l = 0; ci_l < CIB; ci_l++) {
            const float* inc = in + (b * CIN + ci0 + ci_l) * IH * IW;
            float* ts = tile + ci_l * 2312;
#pragma unroll
            for (int k = 0; k < 9; k++) {
                int row = tr + 4 * k;
                if (row < 34) {
                    int gy = y0 + row;
                    bool v = vx_m && (unsigned)gy < (unsigned)DH;
                    int iy = UPS ? (gy >> 1) : gy;
                    ts[row * 68 + tc] = v ? inc[iy * IW + ix_m] : 0.f;
                }
            }
            if (t < 136) {
                int gy = y0 + trow_t;
                bool v = vx_t && (unsigned)gy < (unsigned)DH;
                int iy = UPS ? (gy >> 1) : gy;
                ts[trow_t * 68 + 64 + (t & 3)] = v ? inc[iy * IW + ix_t] : 0.f;
            }
        }
        __syncthreads();

        // ---- compute CIB channels
#pragma unroll
        for (int ci_l = 0; ci_l < CIB; ci_l++) {
            const float* tci = tile + ci_l * 2312;
            float rv[4][6];
#pragma unroll
            for (int r = 0; r < 4; r++) {
                const float* p = &tci[(2 * ty + r) * 68 + 4 * tx];
                float4 a = *(const float4*)p;
                float2 b2 = *(const float2*)(p + 4);
                rv[r][0] = a.x; rv[r][1] = a.y; rv[r][2] = a.z; rv[r][3] = a.w;
                rv[r][4] = b2.x; rv[r][5] = b2.y;
            }
            const ulonglong2* wsc = (const ulonglong2*)(ws2 + ci_l * 36);
#pragma unroll
            for (int ky = 0; ky < 3; ky++) {
#pragma unroll
                for (int kx = 0; kx < 3; kx++) {
                    const int k = ky * 3 + kx;
                    ulonglong2 wA = wsc[k * 2];
                    ulonglong2 wB = wsc[k * 2 + 1];
#pragma unroll
                    for (int py = 0; py < 2; py++) {
#pragma unroll
                        for (int px = 0; px < 4; px++) {
                            float v = rv[py + ky][px + kx];
                            ULL vv = pack2(v, v);
                            acc[py][px][0] = fma2(vv, wA.x, acc[py][px][0]);
                            acc[py][px][1] = fma2(vv, wA.y, acc[py][px][1]);
                            acc[py][px][2] = fma2(vv, wB.x, acc[py][px][2]);
                            acc[py][px][3] = fma2(vv, wB.y, acc[py][px][3]);
                        }
                    }
                }
            }
        }
        __syncthreads();
    }

    // ---- fused 1x1-conv skip, 4 cs channels per sync round ----
    if (SKIP == 2) {
#pragma unroll 1
        for (int cs0 = 0; cs0 < CSKIP; cs0 += 4) {
#pragma unroll
            for (int cs_l = 0; cs_l < 4; cs_l++) {
                const float* sp = skip_in + (b * CSKIP + cs0 + cs_l) * OH * OW
                                + (blockIdx.y * 32) * OW + blockIdx.x * 64;
#pragma unroll
                for (int j = 0; j < 8; j++) {
                    int i = t + 256 * j;
                    int row = i >> 6, col = i & 63;
                    tile[cs_l * 2048 + i] = sp[row * OW + col];
                }
            }
            if (t < 16) {
                int cs_l = t >> 2, p = t & 3;
                int ca = co0 + 2 * p;
                float wa = (ca < COUT) ? skip_w[ca * CSKIP + cs0 + cs_l] : 0.f;
                float wb = (ca + 1 < COUT) ? skip_w[(ca + 1) * CSKIP + cs0 + cs_l] : 0.f;
                ws2[t] = pack2(wa, wb);
            }
            __syncthreads();
#pragma unroll
            for (int cs_l = 0; cs_l < 4; cs_l++) {
                ulonglong2 wA = ((const ulonglong2*)ws2)[cs_l * 2];
                ulonglong2 wB = ((const ulonglong2*)ws2)[cs_l * 2 + 1];
#pragma unroll
                for (int py = 0; py < 2; py++) {
                    float4 s4 = *(const float4*)&tile[cs_l * 2048 + (2 * ty + py) * 64 + 4 * tx];
                    float sv[4] = {s4.x, s4.y, s4.z, s4.w};
#pragma unroll
                    for (int px = 0; px < 4; px++) {
                        ULL vv = pack2(sv[px], sv[px]);
                        acc[py][px][0] = fma2(vv, wA.x, acc[py][px][0]);
                        acc[py][px][1] = fma2(vv, wA.y, acc[py][px][1]);
                        acc[py][px][2] = fma2(vv, wB.x, acc[py][px][2]);
                        acc[py][px][3] = fma2(vv, wB.y, acc[py][px][3]);
                    }
                }
            }
            __syncthreads();
        }
    }

    // ---- epilogue: bias (+skip) (+relu), float4 stores ----
    float bv[8];
#pragma unroll
    for (int c = 0; c < 8; c++) bv[c] = (co0 + c < COUT) ? bias[co0 + c] : 0.f;

#pragma unroll
    for (int c = 0; c < 8; c++) {
        const int co = co0 + c;
        if (co < COUT) {
            const int p = c >> 1, hi = c & 1;
#pragma unroll
            for (int py = 0; py < 2; py++) {
                float o[4];
#pragma unroll
                for (int px = 0; px < 4; px++) {
                    float a0, a1;
                    unpack2(acc[py][px][p], a0, a1);
                    o[px] = (hi ? a1 : a0) + bv[c];
                }
                const int base = ((b * COUT + co) * OH + oy0 + py) * OW + ox0;
                if (SKIP == 1) {
                    float4 s = *(const float4*)&skip_in[base];
                    o[0] += s.x; o[1] += s.y; o[2] += s.z; o[3] += s.w;
                }
                if (SKIP == 2) {
                    float sb = skip_b[co];
#pragma unroll
                    for (int px = 0; px < 4; px++) o[px] += sb;
                }
                if (RELU) {
#pragma unroll
                    for (int px = 0; px < 4; px++) o[px] = fmaxf(o[px], 0.f);
                }
                float4 ov; ov.x = o[0]; ov.y = o[1]; ov.z = o[2]; ov.w = o[3];
                *(float4*)&out[base] = ov;
            }
        }
    }
}

// ---------------------------------------------------------------------------
// OLD direct conv — retained for the stride-2 downsample layer (OUTC=32 now).
// ---------------------------------------------------------------------------
template <int CIN, int OUTC, int STRIDE, bool RELU>
__global__ void __launch_bounds__(256) conv3x3_k(
    const float* __restrict__ in, const float* __restrict__ wgt,
    const float* __restrict__ bias,
    float* __restrict__ out,
    int IH, int IW, int OH, int OW, int COUT, int nG)
{
    constexpr int TS = 16 * STRIDE + 2;
    constexpr int NP = OUTC / 2;
    __shared__ float tile[TS * TS];
    __shared__ ULL ws2[9 * NP];

    const int tx = threadIdx.x, ty = threadIdx.y;
    const int tid = ty * 16 + tx;
    const int bz = blockIdx.z;
    const int b = bz / nG;
    const int co0 = (bz - b * nG) * OUTC;
    const int oy = blockIdx.y * 16 + ty;
    const int ox = blockIdx.x * 16 + tx;
    const int y0 = blockIdx.y * 16 * STRIDE - 1;
    const int x0 = blockIdx.x * 16 * STRIDE - 1;

    ULL acc[NP];
#pragma unroll
    for (int p = 0; p < NP; p++) acc[p] = 0ull;

#pragma unroll 1
    for (int ci = 0; ci < CIN; ci++) {
        const float* inc = in + (b * CIN + ci) * IH * IW;
        for (int i = tid; i < TS * TS; i += 256) {
            int sy = i / TS, sx = i - sy * TS;
            int gy = y0 + sy, gx = x0 + sx;
            float v = 0.f;
            if ((unsigned)gy < (unsigned)IH && (unsigned)gx < (unsigned)IW)
                v = inc[gy * IW + gx];
            tile[i] = v;
        }
        if (tid < 9 * NP) {
            int k = tid / NP, p = tid - k * NP;
            int ca = co0 + 2 * p;
            float wa = (ca < COUT) ? wgt[(ca * CIN + ci) * 9 + k] : 0.f;
            float wb = (ca + 1 < COUT) ? wgt[((ca + 1) * CIN + ci) * 9 + k] : 0.f;
            ws2[tid] = pack2(wa, wb);
        }
        __syncthreads();

#pragma unroll
        for (int ky = 0; ky < 3; ky++) {
#pragma unroll
            for (int kx = 0; kx < 3; kx++) {
                float v = tile[(ty * STRIDE + ky) * TS + tx * STRIDE + kx];
                ULL vv = pack2(v, v);
                const ULL* wrow = &ws2[(ky * 3 + kx) * NP];
#pragma unroll
                for (int p = 0; p < NP; p++) acc[p] = fma2(vv, wrow[p], acc[p]);
            }
        }
        __syncthreads();
    }

    float accf[OUTC];
#pragma unroll
    for (int p = 0; p < NP; p++) unpack2(acc[p], accf[2 * p], accf[2 * p + 1]);

#pragma unroll
    for (int c = 0; c < OUTC; c++) {
        int co = co0 + c;
        if (co >= COUT) break;
        float a = accf[c] + bias[co];
        if (RELU) a = fmaxf(a, 0.f);
        out[((b * COUT + co) * OH + oy) * OW + ox] = a;
    }
}

// ---------------------------------------------------------------------------
// XLA-style warp row reduction of sum(x*x) over 128 elements.
// ---------------------------------------------------------------------------
__device__ __forceinline__ float warp_sumsq_128(const float* __restrict__ x, int lane)
{
    float s = 0.f;
#pragma unroll
    for (int i = 0; i < 4; i++) {
        float v = x[lane + 32 * i];
        s = __fadd_rn(s, __fmul_rn(v, v));
    }
#pragma unroll
    for (int off = 16; off > 0; off >>= 1)
        s = __fadd_rn(s, __shfl_down_sync(0xffffffffu, s, off));
    return s;
}

__global__ void __launch_bounds__(256) prep_cnorm_k(const float* __restrict__ cb)
{
    if (blockIdx.x == 0 && threadIdx.x == 0) g_loss = 0.0;
    int warp = (blockIdx.x * 256 + threadIdx.x) >> 5;
    int lane = threadIdx.x & 31;
    if (warp < 1024) {
        float s = warp_sumsq_128(cb + warp * 128, lane);
        if (lane == 0) g_cnorm[warp] = s;
    }
}

__global__ void __launch_bounds__(256) transpose_cb_k(const float* __restrict__ cb)
{
    int i = blockIdx.x * 256 + threadIdx.x;
    int code = i >> 7, k = i & 127;
    g_cbT[k * 1024 + code] = cb[i];
}

// ---------------------------------------------------------------------------
// Quantizer (unchanged — arithmetic is load-bearing):
// d = fl( fl(znorm - 2*dot) + cnorm ), sequential-k fp32 FMA chains,
// lexicographic argmin, straight-through fl(z + fl(q - z)).
// ---------------------------------------------------------------------------
__global__ void __launch_bounds__(256) quantize_k(
    const float* __restrict__ z, const float* __restrict__ cb,
    float* __restrict__ qst)
{
    __shared__ float ct[8 * 1024];
    __shared__ float zs[16 * 128];
    __shared__ float znorm_s[16];
    __shared__ float cand_d[16][8];
    __shared__ int   cand_i[16][8];
    __shared__ int   kbest_s[16];
    __shared__ double red[256];

    const int t = threadIdx.x;
    const int lane = t & 31, w = t >> 5;
    const long long row0 = (long long)blockIdx.x * 16;

    {
        const float4* zg = (const float4*)(z + row0 * 128);
        float4* z4 = (float4*)zs;
#pragma unroll
        for (int j = 0; j < 2; j++) z4[t + 256 * j] = zg[t + 256 * j];
    }
    __syncthreads();

#pragma unroll
    for (int rr = 0; rr < 2; rr++) {
        int r = w + 8 * rr;
        float s = warp_sumsq_128(zs + r * 128, lane);
        if (lane == 0) znorm_s[r] = s;
    }

    ULL acc[16][2];
#pragma unroll
    for (int r = 0; r < 16; r++) { acc[r][0] = 0ull; acc[r][1] = 0ull; }

#pragma unroll 1
    for (int kt = 0; kt < 16; kt++) {
        __syncthreads();
        {
            const float4* gt = (const float4*)(g_cbT + kt * 8 * 1024);
            float4* c4s = (float4*)ct;
#pragma unroll
            for (int j = 0; j < 8; j++) c4s[t + 256 * j] = gt[t + 256 * j];
        }
        __syncthreads();
#pragma unroll
        for (int kk = 0; kk < 8; kk++) {
            float4 c4 = ((const float4*)ct)[kk * 256 + t];
            ULL cab = pack2(c4.x, c4.y);
            ULL ccd = pack2(c4.z, c4.w);
            const int k = kt * 8 + kk;
#pragma unroll
            for (int r = 0; r < 16; r++) {
                float zk = zs[r * 128 + k];
                ULL zz = pack2(zk, zk);
                acc[r][0] = fma2(zz, cab, acc[r][0]);
                acc[r][1] = fma2(zz, ccd, acc[r][1]);
            }
        }
    }
    __syncthreads();

    float4 cn4 = *(const float4*)(g_cnorm + 4 * t);
#pragma unroll
    for (int r = 0; r < 16; r++) {
        float a, b, c, d;
        unpack2(acc[r][0], a, b);
        unpack2(acc[r][1], c, d);
        float zn = znorm_s[r];
        float d0 = __fadd_rn(__fsub_rn(zn, __fmul_rn(2.f, a)), cn4.x);
        float d1 = __fadd_rn(__fsub_rn(zn, __fmul_rn(2.f, b)), cn4.y);
        float d2 = __fadd_rn(__fsub_rn(zn, __fmul_rn(2.f, c)), cn4.z);
        float d3 = __fadd_rn(__fsub_rn(zn, __fmul_rn(2.f, d)), cn4.w);
        float bv = d0; int bi = 4 * t;
        if (d1 < bv) { bv = d1; bi = 4 * t + 1; }
        if (d2 < bv) { bv = d2; bi = 4 * t + 2; }
        if (d3 < bv) { bv = d3; bi = 4 * t + 3; }
#pragma unroll
        for (int off = 16; off > 0; off >>= 1) {
            float ov = __shfl_down_sync(0xffffffffu, bv, off);
            int   oi = __shfl_down_sync(0xffffffffu, bi, off);
            if (ov < bv || (ov == bv && oi < bi)) { bv = ov; bi = oi; }
        }
        if (lane == 0) { cand_d[r][w] = bv; cand_i[r][w] = bi; }
    }
    __syncthreads();
    if (t < 16) {
        float bv = cand_d[t][0]; int bi = cand_i[t][0];
#pragma unroll
        for (int j = 1; j < 8; j++) {
            float ov = cand_d[t][j]; int oi = cand_i[t][j];
            if (ov < bv || (ov == bv && oi < bi)) { bv = ov; bi = oi; }
        }
        kbest_s[t] = bi;
    }
    __syncthreads();

    double ls = 0.0;
#pragma unroll
    for (int j = 0; j < 8; j++) {
        int e = j * 256 + t;
        int r = e >> 7, col = e & 127;
        float zv = zs[r * 128 + col];
        float qv = cb[kbest_s[r] * 128 + col];
        float qz = __fsub_rn(qv, zv);
        float st = __fadd_rn(zv, qz);
        qst[(row0 + r) * 128 + col] = st;
        ls += (double)qz * (double)qz;
    }
    red[t] = ls;
    __syncthreads();
    for (int s = 128; s > 0; s >>= 1) {
        if (t < s) red[t] += red[t + s];
        __syncthreads();
    }
    if (t == 0) atomicAdd(&g_loss, red[0]);
}

__global__ void finish_k(float* __restrict__ out, int start, int total)
{
    float v = (float)(1.25 * g_loss / 16777216.0);
    for (int i = start + threadIdx.x; i < total; i += 32) out[i] = v;
}

// ---------------------------------------------------------------------------
extern "C" void kernel_launch(void* const* d_in, const int* in_sizes, int n_in,
                              void* d_out, int out_size)
{
    const float* x          = (const float*)d_in[0];
    const float* enc_in_w   = (const float*)d_in[1];
    const float* enc_in_b   = (const float*)d_in[2];
    const float* rb0_w1     = (const float*)d_in[3];
    const float* rb0_b1     = (const float*)d_in[4];
    const float* rb0_w2     = (const float*)d_in[5];
    const float* rb0_b2     = (const float*)d_in[6];
    const float* rb1_w1     = (const float*)d_in[7];
    const float* rb1_b1     = (const float*)d_in[8];
    const float* rb1_w2     = (const float*)d_in[9];
    const float* rb1_b2     = (const float*)d_in[10];
    const float* rb1_ws     = (const float*)d_in[11];
    const float* rb1_bs     = (const float*)d_in[12];
    const float* down_w     = (const float*)d_in[13];
    const float* down_b     = (const float*)d_in[14];
    const float* codebook   = (const float*)d_in[15];
    const float* d1_w1      = (const float*)d_in[16];
    const float* d1_b1      = (const float*)d_in[17];
    const float* d1_w2      = (const float*)d_in[18];
    const float* d1_b2      = (const float*)d_in[19];
    const float* up_w       = (const float*)d_in[20];
    const float* up_b       = (const float*)d_in[21];
    const float* d0_w1      = (const float*)d_in[22];
    const float* d0_b1      = (const float*)d_in[23];
    const float* d0_w2      = (const float*)d_in[24];
    const float* d0_b2      = (const float*)d_in[25];
    const float* out_w      = (const float*)d_in[26];
    const float* out_b      = (const float*)d_in[27];
    float* out = (float*)d_out;

    float *bufA, *bufB, *bufC;
    cudaGetSymbolAddress((void**)&bufA, g_bufA);
    cudaGetSymbolAddress((void**)&bufB, g_bufB);
    cudaGetSymbolAddress((void**)&bufC, g_bufC);

    const int B = 8;
    dim3 G256_64(4, 8, B * 8);     // 256x256, 64 outch (8 groups)
    dim3 G256_128(4, 8, B * 16);   // 256x256, 128 outch (16 groups)
    dim3 G128_128(2, 4, B * 16);   // 128x128, 128 outch
    dim3 G256_3(4, 8, B * 1);      // 256x256, 3 outch
    dim3 blk_old(16, 16);
    dim3 g128_old(8, 8, B * 4);    // stride-2 layer, OUTC=32 -> 4 groups

    // quantizer prep (independent of encoder)
    transpose_cb_k<<<512, 256>>>(codebook);
    prep_cnorm_k<<<128, 256>>>(codebook);

    // ---- encoder ----
    conv3x3n_k<3, 3, false, 0, false><<<G256_64, 256>>>(
        x, enc_in_w, enc_in_b, nullptr, nullptr, nullptr, bufA,
        256, 256, 256, 256, 64, 0, 8);
    conv3x3n_k<64, 4, true, 0, false><<<G256_64, 256>>>(
        bufA, rb0_w1, rb0_b1, nullptr, nullptr, nullptr, bufB,
        256, 256, 256, 256, 64, 0, 8);
    conv3x3n_k<64, 4, true, 1, false><<<G256_64, 256>>>(
        bufB, rb0_w2, rb0_b2, bufA, nullptr, nullptr, bufC,
        256, 256, 256, 256, 64, 0, 8);
    conv3x3n_k<64, 4, true, 0, false><<<G256_128, 256>>>(
        bufC, rb1_w1, rb1_b1, nullptr, nullptr, nullptr, bufA,
        256, 256, 256, 256, 128, 0, 16);
    conv3x3n_k<128, 4, true, 2, false><<<G256_128, 256>>>(
        bufA, rb1_w2, rb1_b2, bufC, rb1_ws, rb1_bs, bufB,
        256, 256, 256, 256, 128, 64, 16);
    conv3x3_k<128, 32, 2, true><<<g128_old, blk_old>>>(
        bufB, down_w, down_b, bufC,
        256, 256, 128, 128, 128, 4);

    // ---- quantizer ----
    quantize_k<<<8192, 256>>>(bufC, codebook, bufA);   // q_st -> bufA

    // ---- decoder ----
    conv3x3n_k<128, 4, true, 0, false><<<G128_128, 256>>>(
        bufA, d1_w1, d1_b1, nullptr, nullptr, nullptr, bufB,
        128, 128, 128, 128, 128, 0, 16);
    conv3x3n_k<128, 4, true, 1, false><<<G128_128, 256>>>(
        bufB, d1_w2, d1_b2, bufA, nullptr, nullptr, bufC,
        128, 128, 128, 128, 128, 0, 16);
    conv3x3n_k<128, 4, true, 0, true><<<G256_64, 256>>>(
        bufC, up_w, up_b, nullptr, nullptr, nullptr, bufA,
        128, 128, 256, 256, 64, 0, 8);
    conv3x3n_k<64, 4, true, 0, false><<<G256_64, 256>>>(
        bufA, d0_w1, d0_b1, nullptr, nullptr, nullptr, bufB,
        256, 256, 256, 256, 64, 0, 8);
    conv3x3n_k<64, 4, true, 1, false><<<G256_64, 256>>>(
        bufB, d0_w2, d0_b2, bufA, nullptr, nullptr, bufC,
        256, 256, 256, 256, 64, 0, 8);
    conv3x3n_k<64, 4, false, 0, false><<<G256_3, 256>>>(
        bufC, out_w, out_b, nullptr, nullptr, nullptr, out,
        256, 256, 256, 256, 3, 0, 1);

    const int recon = 8 * 3 * 256 * 256;
    if (out_size > recon) finish_k<<<1, 32>>>(out, recon, out_size);
}

// round 7
// speedup vs baseline: 1.9272x; 1.1889x over previous
#include <cuda_runtime.h>
#include <cuda_bf16.h>

// ---------------------------------------------------------------------------
// VQ-VAE forward on GB300 (sm_103a).
// R7: cp.async double-buffered staging (overlap LDG with FMA), all weights
// preloaded to smem, new pipelined stride-2 downsample kernel.
// Per-accumulator FMA order unchanged -> bit-identical z / argmin / recon.
// ---------------------------------------------------------------------------

#define ULL unsigned long long

__device__ __forceinline__ ULL pack2(float a, float b) {
    ULL r; asm("mov.b64 %0, {%1, %2};" : "=l"(r) : "f"(a), "f"(b)); return r;
}
__device__ __forceinline__ void unpack2(ULL v, float& a, float& b) {
    asm("mov.b64 {%0, %1}, %2;" : "=f"(a), "=f"(b) : "l"(v));
}
__device__ __forceinline__ ULL fma2(ULL a, ULL b, ULL c) {
    ULL d; asm("fma.rn.f32x2 %0, %1, %2, %3;" : "=l"(d) : "l"(a), "l"(b), "l"(c)); return d;
}

// cp.async helpers (4-byte, zero-fill when invalid)
__device__ __forceinline__ void cpa4(unsigned dst, const void* src, bool v) {
    int sz = v ? 4 : 0;
    asm volatile("cp.async.ca.shared.global [%0], [%1], 4, %2;"
                 :: "r"(dst), "l"(src), "r"(sz));
}
__device__ __forceinline__ void cp_commit() {
    asm volatile("cp.async.commit_group;");
}
template <int N> __device__ __forceinline__ void cp_wait() {
    asm volatile("cp.async.wait_group %0;" :: "n"(N));
}

// Scratch buffers (max tensor: 8 x 128 x 256 x 256 fp32 = 256 MB each)
__device__ float g_bufA[8 * 128 * 256 * 256];
__device__ float g_bufB[8 * 128 * 256 * 256];
__device__ float g_bufC[8 * 128 * 256 * 256];
__device__ float g_cbT[128 * 1024];
__device__ float g_cnorm[1024];
__device__ double g_loss;

// ---------------------------------------------------------------------------
// Stride-1 register-tiled conv, cp.async pipelined.
// Block: 256 threads -> 64(w) x 32(h) tile, 8 output channels.
// Thread: 2x4 px as 32 f32x2 accumulators.
// Dynamic smem: [2 x CIB x 34*68 floats tiles][CIN x 36 ULL weights]
// ---------------------------------------------------------------------------
template <int CIN, int CIB, bool RELU, int SKIP, bool UPS>
__global__ void __launch_bounds__(256, 2) conv3x3n_k(
    const float* __restrict__ in, const float* __restrict__ wgt,
    const float* __restrict__ bias,
    const float* __restrict__ skip_in, const float* __restrict__ skip_w,
    const float* __restrict__ skip_b,
    float* __restrict__ out,
    int IH, int IW, int OH, int OW, int COUT, int CSKIP, int nG)
{
    extern __shared__ __align__(16) char smem_raw[];
    float* tiles = (float*)smem_raw;                                   // 2*CIB*2312
    ULL* wall = (ULL*)(smem_raw + 2 * CIB * 2312 * sizeof(float));     // CIN*36

    const int t = threadIdx.x;
    const int tx = t & 15, ty = t >> 4;
    const int b = blockIdx.z / nG;
    const int co0 = (blockIdx.z - b * nG) * 8;
    const int ox0 = blockIdx.x * 64 + 4 * tx;
    const int oy0 = blockIdx.y * 32 + 2 * ty;
    const int x0 = blockIdx.x * 64 - 1;
    const int y0 = blockIdx.y * 32 - 1;
    const int DH = UPS ? IH * 2 : IH;
    const int DW = UPS ? IW * 2 : IW;

    // hoisted staging coordinates
    const int tr = t >> 6;          // main: col tc, rows tr+4k
    const int tc = t & 63;
    const int gx_m = x0 + tc;
    const bool vx_m = (unsigned)gx_m < (unsigned)DW;
    const int ix_m = UPS ? (gx_m >> 1) : gx_m;
    const int trow_t = t >> 2;      // tail: cols 64..67, rows 0..33 (t < 136)
    const int gx_t = x0 + 64 + (t & 3);
    const bool vx_t = (unsigned)gx_t < (unsigned)DW;
    const int ix_t = UPS ? (gx_t >> 1) : gx_t;

    // preload ALL weight pairs: wall[ci*36 + k*4 + p] = (w[co0+2p], w[co0+2p+1])
    for (int e = t; e < CIN * 36; e += 256) {
        int ci = e / 36, r = e - ci * 36;
        int k = r >> 2, p = r & 3;
        int ca = co0 + 2 * p;
        float wa = (ca < COUT) ? wgt[(ca * CIN + ci) * 9 + k] : 0.f;
        float wb = (ca + 1 < COUT) ? wgt[((ca + 1) * CIN + ci) * 9 + k] : 0.f;
        wall[e] = pack2(wa, wb);
    }

    const unsigned tiles_s = (unsigned)__cvta_generic_to_shared(tiles);

    auto stage = [&](int ci0, int buf) {
        unsigned tb = tiles_s + buf * (CIB * 2312 * 4);
#pragma unroll
        for (int ci_l = 0; ci_l < CIB; ci_l++) {
            const float* inc = in + (b * CIN + ci0 + ci_l) * (IH * IW);
            unsigned ts = tb + ci_l * (2312 * 4);
#pragma unroll
            for (int k = 0; k < 9; k++) {
                int row = tr + 4 * k;
                if (row < 34) {
                    int gy = y0 + row;
                    bool v = vx_m && (unsigned)gy < (unsigned)DH;
                    int iy = UPS ? (gy >> 1) : gy;
                    const float* sp = inc + (v ? (iy * IW + ix_m) : 0);
                    cpa4(ts + (row * 68 + tc) * 4, sp, v);
                }
            }
            if (t < 136) {
                int gy = y0 + trow_t;
                bool v = vx_t && (unsigned)gy < (unsigned)DH;
                int iy = UPS ? (gy >> 1) : gy;
                const float* sp = inc + (v ? (iy * IW + ix_t) : 0);
                cpa4(ts + (trow_t * 68 + 64 + (t & 3)) * 4, sp, v);
            }
        }
        cp_commit();
    };

    ULL acc[2][4][4];
#pragma unroll
    for (int py = 0; py < 2; py++)
#pragma unroll
        for (int px = 0; px < 4; px++)
#pragma unroll
            for (int p = 0; p < 4; p++) acc[py][px][p] = 0ull;

    constexpr int NR = CIN / CIB;
    stage(0, 0);

#pragma unroll 1
    for (int i = 0; i < NR; i++) {
        if (i + 1 < NR) { stage((i + 1) * CIB, (i + 1) & 1); cp_wait<1>(); }
        else            { cp_wait<0>(); }
        __syncthreads();
        const float* tbuf = tiles + (i & 1) * (CIB * 2312);
#pragma unroll
        for (int ci_l = 0; ci_l < CIB; ci_l++) {
            const float* tci = tbuf + ci_l * 2312;
            float rv[4][6];
#pragma unroll
            for (int r = 0; r < 4; r++) {
                const float* p = &tci[(2 * ty + r) * 68 + 4 * tx];
                float4 a = *(const float4*)p;
                float2 b2 = *(const float2*)(p + 4);
                rv[r][0] = a.x; rv[r][1] = a.y; rv[r][2] = a.z; rv[r][3] = a.w;
                rv[r][4] = b2.x; rv[r][5] = b2.y;
            }
            const ulonglong2* wsc = (const ulonglong2*)(wall + (i * CIB + ci_l) * 36);
#pragma unroll
            for (int ky = 0; ky < 3; ky++) {
#pragma unroll
                for (int kx = 0; kx < 3; kx++) {
                    const int k = ky * 3 + kx;
                    ulonglong2 wA = wsc[k * 2];
                    ulonglong2 wB = wsc[k * 2 + 1];
#pragma unroll
                    for (int py = 0; py < 2; py++) {
#pragma unroll
                        for (int px = 0; px < 4; px++) {
                            float v = rv[py + ky][px + kx];
                            ULL vv = pack2(v, v);
                            acc[py][px][0] = fma2(vv, wA.x, acc[py][px][0]);
                            acc[py][px][1] = fma2(vv, wA.y, acc[py][px][1]);
                            acc[py][px][2] = fma2(vv, wB.x, acc[py][px][2]);
                            acc[py][px][3] = fma2(vv, wB.y, acc[py][px][3]);
                        }
                    }
                }
            }
        }
        __syncthreads();
    }

    // fused 1x1-conv skip, 4 cs channels per sync round
    if (SKIP == 2) {
#pragma unroll 1
        for (int cs0 = 0; cs0 < CSKIP; cs0 += 4) {
#pragma unroll
            for (int cs_l = 0; cs_l < 4; cs_l++) {
                const float* sp = skip_in + (b * CSKIP + cs0 + cs_l) * OH * OW
                                + (blockIdx.y * 32) * OW + blockIdx.x * 64;
#pragma unroll
                for (int j = 0; j < 8; j++) {
                    int i = t + 256 * j;
                    int row = i >> 6, col = i & 63;
                    tiles[cs_l * 2048 + i] = sp[row * OW + col];
                }
            }
            if (t < 16) {
                int cs_l = t >> 2, p = t & 3;
                int ca = co0 + 2 * p;
                float wa = (ca < COUT) ? skip_w[ca * CSKIP + cs0 + cs_l] : 0.f;
                float wb = (ca + 1 < COUT) ? skip_w[(ca + 1) * CSKIP + cs0 + cs_l] : 0.f;
                wall[t] = pack2(wa, wb);
            }
            __syncthreads();
#pragma unroll
            for (int cs_l = 0; cs_l < 4; cs_l++) {
                ulonglong2 wA = ((const ulonglong2*)wall)[cs_l * 2];
                ulonglong2 wB = ((const ulonglong2*)wall)[cs_l * 2 + 1];
#pragma unroll
                for (int py = 0; py < 2; py++) {
                    float4 s4 = *(const float4*)&tiles[cs_l * 2048 + (2 * ty + py) * 64 + 4 * tx];
                    float sv[4] = {s4.x, s4.y, s4.z, s4.w};
#pragma unroll
                    for (int px = 0; px < 4; px++) {
                        ULL vv = pack2(sv[px], sv[px]);
                        acc[py][px][0] = fma2(vv, wA.x, acc[py][px][0]);
                        acc[py][px][1] = fma2(vv, wA.y, acc[py][px][1]);
                        acc[py][px][2] = fma2(vv, wB.x, acc[py][px][2]);
                        acc[py][px][3] = fma2(vv, wB.y, acc[py][px][3]);
                    }
                }
            }
            __syncthreads();
        }
    }

    // epilogue
    float bv[8];
#pragma unroll
    for (int c = 0; c < 8; c++) bv[c] = (co0 + c < COUT) ? bias[co0 + c] : 0.f;

#pragma unroll
    for (int c = 0; c < 8; c++) {
        const int co = co0 + c;
        if (co < COUT) {
            const int p = c >> 1, hi = c & 1;
#pragma unroll
            for (int py = 0; py < 2; py++) {
                float o[4];
#pragma unroll
                for (int px = 0; px < 4; px++) {
                    float a0, a1;
                    unpack2(acc[py][px][p], a0, a1);
                    o[px] = (hi ? a1 : a0) + bv[c];
                }
                const int base = ((b * COUT + co) * OH + oy0 + py) * OW + ox0;
                if (SKIP == 1) {
                    float4 s = *(const float4*)&skip_in[base];
                    o[0] += s.x; o[1] += s.y; o[2] += s.z; o[3] += s.w;
                }
                if (SKIP == 2) {
                    float sb = skip_b[co];
#pragma unroll
                    for (int px = 0; px < 4; px++) o[px] += sb;
                }
                if (RELU) {
#pragma unroll
                    for (int px = 0; px < 4; px++) o[px] = fmaxf(o[px], 0.f);
                }
                float4 ov; ov.x = o[0]; ov.y = o[1]; ov.z = o[2]; ov.w = o[3];
                *(float4*)&out[base] = ov;
            }
        }
    }
}

// ---------------------------------------------------------------------------
// Stride-2 conv (relu, no skip), cp.async pipelined.
// Block: 256 threads -> 32x32 output tile, 8 outch. Thread: 2x2 px.
// Input tile per channel: 65x65 stored in 66x68 floats.
// Dynamic smem: [2 x CIB x 4488 floats][CIN x 36 ULL]
// ---------------------------------------------------------------------------
template <int CIN, int CIB>
__global__ void __launch_bounds__(256, 2) conv3x3s2_k(
    const float* __restrict__ in, const float* __restrict__ wgt,
    const float* __restrict__ bias, float* __restrict__ out,
    int IH, int IW, int OH, int OW, int COUT, int nG)
{
    extern __shared__ __align__(16) char smem_raw[];
    float* tiles = (float*)smem_raw;                                   // 2*CIB*4488
    ULL* wall = (ULL*)(smem_raw + 2 * CIB * 4488 * sizeof(float));     // CIN*36

    const int t = threadIdx.x;
    const int tx = t & 15, ty = t >> 4;
    const int b = blockIdx.z / nG;
    const int co0 = (blockIdx.z - b * nG) * 8;
    const int ox0 = blockIdx.x * 32;
    const int oy0 = blockIdx.y * 32;
    const int x0 = blockIdx.x * 64 - 1;
    const int y0 = blockIdx.y * 64 - 1;

    // staging coords: main cols 0..63 (tc), rows tr+4k (k 0..16, row<65);
    // tail: t<65 -> (row=t, col=64)
    const int tr = t >> 6;
    const int tc = t & 63;
    const int gx_m = x0 + tc;
    const bool vx_m = (unsigned)gx_m < (unsigned)IW;
    const int gx_t = x0 + 64;
    const bool vx_t = (unsigned)gx_t < (unsigned)IW;

    for (int e = t; e < CIN * 36; e += 256) {
        int ci = e / 36, r = e - ci * 36;
        int k = r >> 2, p = r & 3;
        int ca = co0 + 2 * p;
        float wa = (ca < COUT) ? wgt[(ca * CIN + ci) * 9 + k] : 0.f;
        float wb = (ca + 1 < COUT) ? wgt[((ca + 1) * CIN + ci) * 9 + k] : 0.f;
        wall[e] = pack2(wa, wb);
    }

    const unsigned tiles_s = (unsigned)__cvta_generic_to_shared(tiles);

    auto stage = [&](int ci0, int buf) {
        unsigned tb = tiles_s + buf * (CIB * 4488 * 4);
#pragma unroll
        for (int ci_l = 0; ci_l < CIB; ci_l++) {
            const float* inc = in + (b * CIN + ci0 + ci_l) * (IH * IW);
            unsigned ts = tb + ci_l * (4488 * 4);
#pragma unroll
            for (int k = 0; k < 17; k++) {
                int row = tr + 4 * k;
                if (row < 65) {
                    int gy = y0 + row;
                    bool v = vx_m && (unsigned)gy < (unsigned)IH;
                    const float* sp = inc + (v ? (gy * IW + gx_m) : 0);
                    cpa4(ts + (row * 68 + tc) * 4, sp, v);
                }
            }
            if (t < 65) {
                int gy = y0 + t;
                bool v = vx_t && (unsigned)gy < (unsigned)IH;
                const float* sp = inc + (v ? (gy * IW + gx_t) : 0);
                cpa4(ts + (t * 68 + 64) * 4, sp, v);
            }
        }
        cp_commit();
    };

    ULL acc[2][2][4];
#pragma unroll
    for (int py = 0; py < 2; py++)
#pragma unroll
        for (int px = 0; px < 2; px++)
#pragma unroll
            for (int p = 0; p < 4; p++) acc[py][px][p] = 0ull;

    constexpr int NR = CIN / CIB;
    stage(0, 0);

#pragma unroll 1
    for (int i = 0; i < NR; i++) {
        if (i + 1 < NR) { stage((i + 1) * CIB, (i + 1) & 1); cp_wait<1>(); }
        else            { cp_wait<0>(); }
        __syncthreads();
        const float* tbuf = tiles + (i & 1) * (CIB * 4488);
#pragma unroll
        for (int ci_l = 0; ci_l < CIB; ci_l++) {
            const float* tci = tbuf + ci_l * 4488;
            float rv[5][6];
#pragma unroll
            for (int r = 0; r < 5; r++) {
                const float* p = &tci[(4 * ty + r) * 68 + 4 * tx];
                float4 a = *(const float4*)p;
                float2 b2 = *(const float2*)(p + 4);
                rv[r][0] = a.x; rv[r][1] = a.y; rv[r][2] = a.z; rv[r][3] = a.w;
                rv[r][4] = b2.x; rv[r][5] = b2.y;
            }
            const ulonglong2* wsc = (const ulonglong2*)(wall + (i * CIB + ci_l) * 36);
#pragma unroll
            for (int ky = 0; ky < 3; ky++) {
#pragma unroll
                for (int kx = 0; kx < 3; kx++) {
                    const int k = ky * 3 + kx;
                    ulonglong2 wA = wsc[k * 2];
                    ulonglong2 wB = wsc[k * 2 + 1];
#pragma unroll
                    for (int py = 0; py < 2; py++) {
#pragma unroll
                        for (int px = 0; px < 2; px++) {
                            float v = rv[2 * py + ky][2 * px + kx];
                            ULL vv = pack2(v, v);
                            acc[py][px][0] = fma2(vv, wA.x, acc[py][px][0]);
                            acc[py][px][1] = fma2(vv, wA.y, acc[py][px][1]);
                            acc[py][px][2] = fma2(vv, wB.x, acc[py][px][2]);
                            acc[py][px][3] = fma2(vv, wB.y, acc[py][px][3]);
                        }
                    }
                }
            }
        }
        __syncthreads();
    }

    // epilogue: bias + relu, float2 stores
#pragma unroll
    for (int c = 0; c < 8; c++) {
        const int co = co0 + c;
        if (co < COUT) {
            const float bb = bias[co];
            const int p = c >> 1, hi = c & 1;
#pragma unroll
            for (int py = 0; py < 2; py++) {
                float o[2];
#pragma unroll
                for (int px = 0; px < 2; px++) {
                    float a0, a1;
                    unpack2(acc[py][px][p], a0, a1);
                    o[px] = fmaxf((hi ? a1 : a0) + bb, 0.f);
                }
                float2 ov; ov.x = o[0]; ov.y = o[1];
                *(float2*)&out[((b * COUT + co) * OH + oy0 + 2 * ty + py) * OW
                               + ox0 + 2 * tx] = ov;
            }
        }
    }
}

// ---------------------------------------------------------------------------
// XLA-style warp row reduction of sum(x*x) over 128 elements.
// ---------------------------------------------------------------------------
__device__ __forceinline__ float warp_sumsq_128(const float* __restrict__ x, int lane)
{
    float s = 0.f;
#pragma unroll
    for (int i = 0; i < 4; i++) {
        float v = x[lane + 32 * i];
        s = __fadd_rn(s, __fmul_rn(v, v));
    }
#pragma unroll
    for (int off = 16; off > 0; off >>= 1)
        s = __fadd_rn(s, __shfl_down_sync(0xffffffffu, s, off));
    return s;
}

__global__ void __launch_bounds__(256) prep_cnorm_k(const float* __restrict__ cb)
{
    if (blockIdx.x == 0 && threadIdx.x == 0) g_loss = 0.0;
    int warp = (blockIdx.x * 256 + threadIdx.x) >> 5;
    int lane = threadIdx.x & 31;
    if (warp < 1024) {
        float s = warp_sumsq_128(cb + warp * 128, lane);
        if (lane == 0) g_cnorm[warp] = s;
    }
}

__global__ void __launch_bounds__(256) transpose_cb_k(const float* __restrict__ cb)
{
    int i = blockIdx.x * 256 + threadIdx.x;
    int code = i >> 7, k = i & 127;
    g_cbT[k * 1024 + code] = cb[i];
}

// ---------------------------------------------------------------------------
// Quantizer (unchanged — arithmetic is load-bearing):
// d = fl( fl(znorm - 2*dot) + cnorm ), sequential-k fp32 FMA chains,
// lexicographic argmin, straight-through fl(z + fl(q - z)).
// ---------------------------------------------------------------------------
__global__ void __launch_bounds__(256) quantize_k(
    const float* __restrict__ z, const float* __restrict__ cb,
    float* __restrict__ qst)
{
    __shared__ float ct[8 * 1024];
    __shared__ float zs[16 * 128];
    __shared__ float znorm_s[16];
    __shared__ float cand_d[16][8];
    __shared__ int   cand_i[16][8];
    __shared__ int   kbest_s[16];
    __shared__ double red[256];

    const int t = threadIdx.x;
    const int lane = t & 31, w = t >> 5;
    const long long row0 = (long long)blockIdx.x * 16;

    {
        const float4* zg = (const float4*)(z + row0 * 128);
        float4* z4 = (float4*)zs;
#pragma unroll
        for (int j = 0; j < 2; j++) z4[t + 256 * j] = zg[t + 256 * j];
    }
    __syncthreads();

#pragma unroll
    for (int rr = 0; rr < 2; rr++) {
        int r = w + 8 * rr;
        float s = warp_sumsq_128(zs + r * 128, lane);
        if (lane == 0) znorm_s[r] = s;
    }

    ULL acc[16][2];
#pragma unroll
    for (int r = 0; r < 16; r++) { acc[r][0] = 0ull; acc[r][1] = 0ull; }

#pragma unroll 1
    for (int kt = 0; kt < 16; kt++) {
        __syncthreads();
        {
            const float4* gt = (const float4*)(g_cbT + kt * 8 * 1024);
            float4* c4s = (float4*)ct;
#pragma unroll
            for (int j = 0; j < 8; j++) c4s[t + 256 * j] = gt[t + 256 * j];
        }
        __syncthreads();
#pragma unroll
        for (int kk = 0; kk < 8; kk++) {
            float4 c4 = ((const float4*)ct)[kk * 256 + t];
            ULL cab = pack2(c4.x, c4.y);
            ULL ccd = pack2(c4.z, c4.w);
            const int k = kt * 8 + kk;
#pragma unroll
            for (int r = 0; r < 16; r++) {
                float zk = zs[r * 128 + k];
                ULL zz = pack2(zk, zk);
                acc[r][0] = fma2(zz, cab, acc[r][0]);
                acc[r][1] = fma2(zz, ccd, acc[r][1]);
            }
        }
    }
    __syncthreads();

    float4 cn4 = *(const float4*)(g_cnorm + 4 * t);
#pragma unroll
    for (int r = 0; r < 16; r++) {
        float a, b, c, d;
        unpack2(acc[r][0], a, b);
        unpack2(acc[r][1], c, d);
        float zn = znorm_s[r];
        float d0 = __fadd_rn(__fsub_rn(zn, __fmul_rn(2.f, a)), cn4.x);
        float d1 = __fadd_rn(__fsub_rn(zn, __fmul_rn(2.f, b)), cn4.y);
        float d2 = __fadd_rn(__fsub_rn(zn, __fmul_rn(2.f, c)), cn4.z);
        float d3 = __fadd_rn(__fsub_rn(zn, __fmul_rn(2.f, d)), cn4.w);
        float bv = d0; int bi = 4 * t;
        if (d1 < bv) { bv = d1; bi = 4 * t + 1; }
        if (d2 < bv) { bv = d2; bi = 4 * t + 2; }
        if (d3 < bv) { bv = d3; bi = 4 * t + 3; }
#pragma unroll
        for (int off = 16; off > 0; off >>= 1) {
            float ov = __shfl_down_sync(0xffffffffu, bv, off);
            int   oi = __shfl_down_sync(0xffffffffu, bi, off);
            if (ov < bv || (ov == bv && oi < bi)) { bv = ov; bi = oi; }
        }
        if (lane == 0) { cand_d[r][w] = bv; cand_i[r][w] = bi; }
    }
    __syncthreads();
    if (t < 16) {
        float bv = cand_d[t][0]; int bi = cand_i[t][0];
#pragma unroll
        for (int j = 1; j < 8; j++) {
            float ov = cand_d[t][j]; int oi = cand_i[t][j];
            if (ov < bv || (ov == bv && oi < bi)) { bv = ov; bi = oi; }
        }
        kbest_s[t] = bi;
    }
    __syncthreads();

    double ls = 0.0;
#pragma unroll
    for (int j = 0; j < 8; j++) {
        int e = j * 256 + t;
        int r = e >> 7, col = e & 127;
        float zv = zs[r * 128 + col];
        float qv = cb[kbest_s[r] * 128 + col];
        float qz = __fsub_rn(qv, zv);
        float st = __fadd_rn(zv, qz);
        qst[(row0 + r) * 128 + col] = st;
        ls += (double)qz * (double)qz;
    }
    red[t] = ls;
    __syncthreads();
    for (int s = 128; s > 0; s >>= 1) {
        if (t < s) red[t] += red[t + s];
        __syncthreads();
    }
    if (t == 0) atomicAdd(&g_loss, red[0]);
}

__global__ void finish_k(float* __restrict__ out, int start, int total)
{
    float v = (float)(1.25 * g_loss / 16777216.0);
    for (int i = start + threadIdx.x; i < total; i += 32) out[i] = v;
}

// ---------------------------------------------------------------------------
extern "C" void kernel_launch(void* const* d_in, const int* in_sizes, int n_in,
                              void* d_out, int out_size)
{
    const float* x          = (const float*)d_in[0];
    const float* enc_in_w   = (const float*)d_in[1];
    const float* enc_in_b   = (const float*)d_in[2];
    const float* rb0_w1     = (const float*)d_in[3];
    const float* rb0_b1     = (const float*)d_in[4];
    const float* rb0_w2     = (const float*)d_in[5];
    const float* rb0_b2     = (const float*)d_in[6];
    const float* rb1_w1     = (const float*)d_in[7];
    const float* rb1_b1     = (const float*)d_in[8];
    const float* rb1_w2     = (const float*)d_in[9];
    const float* rb1_b2     = (const float*)d_in[10];
    const float* rb1_ws     = (const float*)d_in[11];
    const float* rb1_bs     = (const float*)d_in[12];
    const float* down_w     = (const float*)d_in[13];
    const float* down_b     = (const float*)d_in[14];
    const float* codebook   = (const float*)d_in[15];
    const float* d1_w1      = (const float*)d_in[16];
    const float* d1_b1      = (const float*)d_in[17];
    const float* d1_w2      = (const float*)d_in[18];
    const float* d1_b2      = (const float*)d_in[19];
    const float* up_w       = (const float*)d_in[20];
    const float* up_b       = (const float*)d_in[21];
    const float* d0_w1      = (const float*)d_in[22];
    const float* d0_b1      = (const float*)d_in[23];
    const float* d0_w2      = (const float*)d_in[24];
    const float* d0_b2      = (const float*)d_in[25];
    const float* out_w      = (const float*)d_in[26];
    const float* out_b      = (const float*)d_in[27];
    float* out = (float*)d_out;

    float *bufA, *bufB, *bufC;
    cudaGetSymbolAddress((void**)&bufA, g_bufA);
    cudaGetSymbolAddress((void**)&bufB, g_bufB);
    cudaGetSymbolAddress((void**)&bufC, g_bufC);

    // dynamic smem sizes
    const int SM_3   = 2 * 3 * 2312 * 4 + 3 * 36 * 8;     //  56352
    const int SM_64  = 2 * 4 * 2312 * 4 + 64 * 36 * 8;    //  92416
    const int SM_128 = 2 * 4 * 2312 * 4 + 128 * 36 * 8;   // 110848
    const int SM_S2  = 2 * 2 * 4488 * 4 + 128 * 36 * 8;   // 108672

    cudaFuncSetAttribute(conv3x3n_k<3, 3, false, 0, false>,  cudaFuncAttributeMaxDynamicSharedMemorySize, SM_3);
    cudaFuncSetAttribute(conv3x3n_k<64, 4, true, 0, false>,  cudaFuncAttributeMaxDynamicSharedMemorySize, SM_64);
    cudaFuncSetAttribute(conv3x3n_k<64, 4, true, 1, false>,  cudaFuncAttributeMaxDynamicSharedMemorySize, SM_64);
    cudaFuncSetAttribute(conv3x3n_k<64, 4, false, 0, false>, cudaFuncAttributeMaxDynamicSharedMemorySize, SM_64);
    cudaFuncSetAttribute(conv3x3n_k<128, 4, true, 0, false>, cudaFuncAttributeMaxDynamicSharedMemorySize, SM_128);
    cudaFuncSetAttribute(conv3x3n_k<128, 4, true, 1, false>, cudaFuncAttributeMaxDynamicSharedMemorySize, SM_128);
    cudaFuncSetAttribute(conv3x3n_k<128, 4, true, 2, false>, cudaFuncAttributeMaxDynamicSharedMemorySize, SM_128);
    cudaFuncSetAttribute(conv3x3n_k<128, 4, true, 0, true>,  cudaFuncAttributeMaxDynamicSharedMemorySize, SM_128);
    cudaFuncSetAttribute(conv3x3s2_k<128, 2>,                cudaFuncAttributeMaxDynamicSharedMemorySize, SM_S2);

    const int B = 8;
    dim3 G256_64(4, 8, B * 8);     // 256x256, 64 outch
    dim3 G256_128(4, 8, B * 16);   // 256x256, 128 outch
    dim3 G128_128(2, 4, B * 16);   // 128x128, 128 outch
    dim3 G256_3(4, 8, B * 1);      // 256x256, 3 outch
    dim3 GS2(4, 4, B * 16);        // stride-2: 128x128 out, 32x32 tiles

    // quantizer prep (independent of encoder)
    transpose_cb_k<<<512, 256>>>(codebook);
    prep_cnorm_k<<<128, 256>>>(codebook);

    // ---- encoder ----
    conv3x3n_k<3, 3, false, 0, false><<<G256_64, 256, SM_3>>>(
        x, enc_in_w, enc_in_b, nullptr, nullptr, nullptr, bufA,
        256, 256, 256, 256, 64, 0, 8);
    conv3x3n_k<64, 4, true, 0, false><<<G256_64, 256, SM_64>>>(
        bufA, rb0_w1, rb0_b1, nullptr, nullptr, nullptr, bufB,
        256, 256, 256, 256, 64, 0, 8);
    conv3x3n_k<64, 4, true, 1, false><<<G256_64, 256, SM_64>>>(
        bufB, rb0_w2, rb0_b2, bufA, nullptr, nullptr, bufC,
        256, 256, 256, 256, 64, 0, 8);
    conv3x3n_k<64, 4, true, 0, false><<<G256_128, 256, SM_64>>>(
        bufC, rb1_w1, rb1_b1, nullptr, nullptr, nullptr, bufA,
        256, 256, 256, 256, 128, 0, 16);
    conv3x3n_k<128, 4, true, 2, false><<<G256_128, 256, SM_128>>>(
        bufA, rb1_w2, rb1_b2, bufC, rb1_ws, rb1_bs, bufB,
        256, 256, 256, 256, 128, 64, 16);
    conv3x3s2_k<128, 2><<<GS2, 256, SM_S2>>>(
        bufB, down_w, down_b, bufC,
        256, 256, 128, 128, 128, 16);

    // ---- quantizer ----
    quantize_k<<<8192, 256>>>(bufC, codebook, bufA);   // q_st -> bufA

    // ---- decoder ----
    conv3x3n_k<128, 4, true, 0, false><<<G128_128, 256, SM_128>>>(
        bufA, d1_w1, d1_b1, nullptr, nullptr, nullptr, bufB,
        128, 128, 128, 128, 128, 0, 16);
    conv3x3n_k<128, 4, true, 1, false><<<G128_128, 256, SM_128>>>(
        bufB, d1_w2, d1_b2, bufA, nullptr, nullptr, bufC,
        128, 128, 128, 128, 128, 0, 16);
    conv3x3n_k<128, 4, true, 0, true><<<G256_64, 256, SM_128>>>(
        bufC, up_w, up_b, nullptr, nullptr, nullptr, bufA,
        128, 128, 256, 256, 64, 0, 8);
    conv3x3n_k<64, 4, true, 0, false><<<G256_64, 256, SM_64>>>(
        bufA, d0_w1, d0_b1, nullptr, nullptr, nullptr, bufB,
        256, 256, 256, 256, 64, 0, 8);
    conv3x3n_k<64, 4, true, 1, false><<<G256_64, 256, SM_64>>>(
        bufB, d0_w2, d0_b2, bufA, nullptr, nullptr, bufC,
        256, 256, 256, 256, 64, 0, 8);
    conv3x3n_k<64, 4, false, 0, false><<<G256_3, 256, SM_64>>>(
        bufC, out_w, out_b, nullptr, nullptr, nullptr, out,
        256, 256, 256, 256, 3, 0, 1);

    const int recon = 8 * 3 * 256 * 256;
    if (out_size > recon) finish_k<<<1, 32>>>(out, recon, out_size);
}